// round 9
// baseline (speedup 1.0000x reference)
#include <cuda_runtime.h>
#include <cstdint>

#define NTOT 8192
#define BB   8
#define NBAT 1024
#define KK   9
#define CC   32
#define CMID 128
#define MM   9216        // NBAT*KK per batch
#define KSPLIT 9
#define KPART  1024      // MM / KSPLIT
#define NCH    32        // KPART / 32
#define NGRP   16        // b(8) x rowblock(2)
#define HF_GRID 128
#define PG     16        // n per k_prep block
#define PM     (PG * KK) // 144 m per k_prep block

// ---------------- scratch (device globals; no allocation anywhere) ----------
__device__ float  g_convwT[BB * CC * MM];   // [b][c][m], tf32-rounded
__device__ float4 g_abxy[BB * MM];          // (am, bx, by, 0) per m
__device__ float  g_part[KSPLIT * NTOT * CC];
__device__ float  g_x[NTOT * CC];           // leaky(sampled)
__device__ float  g_sx[CC], g_sx2[CC], g_sh[CMID], g_sh2[CMID];
__device__ int    g_sync[NGRP];             // k_main group counters
__device__ int    g_cnt;                    // k_hf barrier counter

// ---------------- helpers ----------------------------------------------------
__device__ __forceinline__ float ex2(float x) {
    float y; asm("ex2.approx.f32 %0, %1;" : "=f"(y) : "f"(x)); return y;
}
__device__ __forceinline__ float tf32r(float x) {   // rna round, keep as float
    uint32_t u; asm("cvt.rna.tf32.f32 %0, %1;" : "=r"(u) : "f"(x));
    return __uint_as_float(u);
}
__device__ __forceinline__ void mma_tf32(float* d, const uint32_t* a,
                                         uint32_t b0, uint32_t b1) {
    asm volatile(
        "mma.sync.aligned.m16n8k8.row.col.f32.tf32.tf32.f32 "
        "{%0,%1,%2,%3}, {%4,%5,%6,%7}, {%8,%9}, {%0,%1,%2,%3};"
        : "+f"(d[0]), "+f"(d[1]), "+f"(d[2]), "+f"(d[3])
        : "r"(a[0]), "r"(a[1]), "r"(a[2]), "r"(a[3]), "r"(b0), "r"(b1));
}

#define LOG2E 1.4426950408889634f
#define C2    (-2.0f * LOG2E)

// ---------------- K1: conv_w^T (tf32-rounded) + abxy + zero counters --------
// grid 512 (16 n per block), 288 threads = (k=tid/32, d=tid%32)
// 4-way ILP in the einsum; staging pad-33; coalesced transposed writeout.
__global__ void __launch_bounds__(288) k_prep(const float* __restrict__ pos,
                                              const float* __restrict__ wts,
                                              const float* __restrict__ kpos,
                                              const float* __restrict__ kw) {
    __shared__ __align__(16) float sw[PG * CC];       // 2 KB
    __shared__ float sp[PG * 2];
    __shared__ float skp[KK * 2];
    __shared__ float st[PM * 33];                     // 19 KB, [m_local][d] pad33
    int tid = threadIdx.x;
    int n0 = blockIdx.x * PG;          // global n
    int b  = n0 >> 10;
    int m0 = (n0 & 1023) * KK;         // m within batch
    if (blockIdx.x == 0) {             // re-zero per replay
        if (tid < CC)   { g_sx[tid] = 0.f; g_sx2[tid] = 0.f; }
        if (tid < CMID) { g_sh[tid] = 0.f; g_sh2[tid] = 0.f; }
        if (tid < NGRP) g_sync[tid] = 0;
        if (tid == NGRP) g_cnt = 0;
    }
    for (int i = tid; i < PG * CC; i += 288) sw[i] = wts[n0 * CC + i];  // 512 elems!
    if (tid < PG * 2)  sp[tid] = pos[n0 * 2 + tid];
    if (tid < KK * 2)  skp[tid] = kpos[tid];
    int k = tid / 32, d = tid % 32;
    float kr[CC];
    #pragma unroll
    for (int c = 0; c < CC; c++) kr[c] = kw[(k * CC + c) * CC + d];
    __syncthreads();
    #pragma unroll
    for (int n = 0; n < PG; n += 2) {
        const float4* s0 = (const float4*)(sw + n * CC);
        const float4* s1 = (const float4*)(sw + (n + 1) * CC);
        float a0 = 0.f, a1 = 0.f, b0 = 0.f, b1 = 0.f;   // 4 independent chains
        #pragma unroll
        for (int q = 0; q < 4; q++) {
            float4 v0 = s0[q], v0h = s0[q + 4];
            float4 v1 = s1[q], v1h = s1[q + 4];
            a0 = fmaf(v0.x,  kr[4*q+0],    a0);
            a1 = fmaf(v0h.x, kr[16+4*q+0], a1);
            b0 = fmaf(v1.x,  kr[4*q+0],    b0);
            b1 = fmaf(v1h.x, kr[16+4*q+0], b1);
            a0 = fmaf(v0.y,  kr[4*q+1],    a0);
            a1 = fmaf(v0h.y, kr[16+4*q+1], a1);
            b0 = fmaf(v1.y,  kr[4*q+1],    b0);
            b1 = fmaf(v1h.y, kr[16+4*q+1], b1);
            a0 = fmaf(v0.z,  kr[4*q+2],    a0);
            a1 = fmaf(v0h.z, kr[16+4*q+2], a1);
            b0 = fmaf(v1.z,  kr[4*q+2],    b0);
            b1 = fmaf(v1h.z, kr[16+4*q+2], b1);
            a0 = fmaf(v0.w,  kr[4*q+3],    a0);
            a1 = fmaf(v0h.w, kr[16+4*q+3], a1);
            b0 = fmaf(v1.w,  kr[4*q+3],    b0);
            b1 = fmaf(v1h.w, kr[16+4*q+3], b1);
        }
        st[(n * KK + k) * 33 + d]       = tf32r(a0 + a1);
        st[((n + 1) * KK + k) * 33 + d] = tf32r(b0 + b1);
    }
    // abxy (144 m's, one per thread)
    if (tid < PM) {
        int n = tid / KK, kk = tid - (tid / KK) * KK;
        float cpx = sp[2 * n]     + skp[2 * kk];
        float cpy = sp[2 * n + 1] + skp[2 * kk + 1];
        float am  = C2 * fmaf(cpx, cpx, cpy * cpy);
        g_abxy[(size_t)b * MM + m0 + tid] =
            make_float4(am, 4.f * LOG2E * cpx, 4.f * LOG2E * cpy, 0.f);
    }
    __syncthreads();
    // transposed writeout: flattened idx = c*144 + mm; consecutive threads ->
    // consecutive mm -> coalesced stores; LDS bank (mm+c)%32 conflict-free.
    #pragma unroll
    for (int it = 0; it < PM * CC / 288; it++) {
        int idx = tid + it * 288;
        int c  = idx / PM;
        int mm = idx - c * PM;
        g_convwT[((size_t)b * CC + c) * MM + m0 + mm] = st[mm * 33 + c];
    }
}

// ---------------- K2: Kmat @ conv_w via mma.sync tf32, fused reduction ------
// grid 144 = b(8) x rowblock(2) x ksplit(9); 512 threads = 16 warps.
// Last CTA of each (b,rb) group reduces the 9 partials, applies leaky,
// writes g_x and accumulates BN-x stats.
__global__ void __launch_bounds__(512) k_main(const float* __restrict__ pos) {
    __shared__ float  sB[2][32 * 36];   // padded rows: bank-conflict-free frags
    __shared__ float4 sAB[2][32];
    __shared__ float  red[512];
    __shared__ int    s_last;
    int tid  = threadIdx.x;
    int w    = tid >> 5, lane = tid & 31;
    int g    = lane >> 2, tg = lane & 3;
    int blk  = blockIdx.x;
    int b   = blk / 18;
    int rem = blk - b * 18;
    int rb  = rem / 9;
    int ks  = rem - rb * 9;
    int ctabase = b * NBAT + rb * 512;
    int rbase   = ctabase + w * 32;
    size_t mbase = (size_t)b * MM + (size_t)ks * KPART;

    // staging mapping: threads 0..255 -> (c = tid>>3, mq = tid&7), float4/chunk
    int sc = tid >> 3, smq = tid & 7;
    const float4* gB  = (const float4*)(g_convwT + ((size_t)b * CC + sc) * MM
                                        + (size_t)ks * KPART) + smq;
    const float4* gAB = g_abxy + mbase;

    // per-lane row data: rows rbase + g + 8u, u = 0..3
    float px[4], py[4], pp[4];
    #pragma unroll
    for (int u = 0; u < 4; u++) {
        float2 p = ((const float2*)pos)[rbase + g + 8 * u];
        px[u] = p.x; py[u] = p.y;
        pp[u] = C2 * fmaf(p.x, p.x, p.y * p.y);
    }
    float acc[2][4][4];
    #pragma unroll
    for (int j = 0; j < 2; j++)
        #pragma unroll
        for (int i = 0; i < 4; i++)
            #pragma unroll
            for (int q = 0; q < 4; q++) acc[j][i][q] = 0.f;

    // stage chunk 0
    if (tid < 256) {
        float4 v = gB[0];
        float* d = &sB[0][sc * 36 + smq * 4];
        d[0] = v.x; d[1] = v.y; d[2] = v.z; d[3] = v.w;
    }
    if (tid < 32) sAB[0][tid] = gAB[tid];
    for (int t = 0; t < NCH; t++) {
        int buf = t & 1;
        __syncthreads();
        if (t + 1 < NCH) {
            if (tid < 256) {
                float4 v = gB[(t + 1) * 8];
                float* d = &sB[buf ^ 1][sc * 36 + smq * 4];
                d[0] = v.x; d[1] = v.y; d[2] = v.z; d[3] = v.w;
            }
            if (tid < 32) sAB[buf ^ 1][tid] = gAB[(t + 1) * 32 + tid];
        }
        #pragma unroll
        for (int s = 0; s < 4; s++) {
            int m0 = s * 8 + tg;
            float4 q0 = sAB[buf][m0];
            float4 q1 = sAB[buf][m0 + 4];
            uint32_t B0[4], B1[4];
            #pragma unroll
            for (int i = 0; i < 4; i++) {
                B0[i] = __float_as_uint(sB[buf][(g + 8 * i) * 36 + m0]);
                B1[i] = __float_as_uint(sB[buf][(g + 8 * i) * 36 + m0 + 4]);
            }
            uint32_t A[2][4];
            #pragma unroll
            for (int j = 0; j < 2; j++) {
                int u0 = 2 * j, u1 = 2 * j + 1;
                A[j][0] = __float_as_uint(ex2(fmaf(q0.y, px[u0], fmaf(q0.z, py[u0], pp[u0] + q0.x))));
                A[j][1] = __float_as_uint(ex2(fmaf(q0.y, px[u1], fmaf(q0.z, py[u1], pp[u1] + q0.x))));
                A[j][2] = __float_as_uint(ex2(fmaf(q1.y, px[u0], fmaf(q1.z, py[u0], pp[u0] + q1.x))));
                A[j][3] = __float_as_uint(ex2(fmaf(q1.y, px[u1], fmaf(q1.z, py[u1], pp[u1] + q1.x))));
            }
            #pragma unroll
            for (int j = 0; j < 2; j++)
                #pragma unroll
                for (int i = 0; i < 4; i++)
                    mma_tf32(acc[j][i], A[j], B0[i], B1[i]);
        }
    }
    // store partials
    #pragma unroll
    for (int j = 0; j < 2; j++) {
        int nr0 = rbase + j * 16 + g;
        #pragma unroll
        for (int i = 0; i < 4; i++) {
            int c = i * 8 + tg * 2;
            *(float2*)&g_part[((size_t)ks * NTOT + nr0) * CC + c] =
                make_float2(acc[j][i][0], acc[j][i][1]);
            *(float2*)&g_part[((size_t)ks * NTOT + nr0 + 8) * CC + c] =
                make_float2(acc[j][i][2], acc[j][i][3]);
        }
    }
    // ---- group finish: last CTA reduces ----
    __threadfence();
    __syncthreads();
    if (tid == 0) s_last = (atomicAdd(&g_sync[b * 2 + rb], 1) == KSPLIT - 1);
    __syncthreads();
    if (!s_last) return;
    __threadfence();
    int c = tid & 31, rs = tid >> 5;    // rs 0..15
    float sx = 0.f, sx2 = 0.f;
    for (int i = 0; i < 32; i++) {
        int n = ctabase + i * 16 + rs;
        size_t o = (size_t)n * CC + c;
        float v = 0.f;
        #pragma unroll
        for (int s = 0; s < KSPLIT; s++) v += g_part[(size_t)s * NTOT * CC + o];
        float x = v >= 0.f ? v : 0.01f * v;
        g_x[o] = x;
        sx += x; sx2 += x * x;
    }
    red[tid] = sx; __syncthreads();
    if (rs == 0) {
        float s = 0.f;
        #pragma unroll
        for (int j = 0; j < 16; j++) s += red[c + 32 * j];
        atomicAdd(&g_sx[c], s);
    }
    __syncthreads(); red[tid] = sx2; __syncthreads();
    if (rs == 0) {
        float s = 0.f;
        #pragma unroll
        for (int j = 0; j < 16; j++) s += red[c + 32 * j];
        atomicAdd(&g_sx2[c], s);
    }
}

// ---------------- K3: fused  xn -> h -> BN(h) -> W2 -> outputs --------------
// grid 128, 512 threads; 64 rows/block; grid-wide spin barrier (all resident).
// dynamic smem layout (floats):
#define HF_SXN  0        // 64*32   = 2048
#define HF_SW1  2048     // 32*128  = 4096
#define HF_SH   6144     // 64*128  = 8192
#define HF_SW2  14336    // 128*34  = 4352
#define HF_SB2  18688    // 48
#define HF_SXS  18736    // 32
#define HF_SXH  18768    // 32
#define HF_SHS  18800    // 128
#define HF_SHH  18928    // 128
#define HF_RED  19056    // 512
#define HF_FLOATS 19568  // 78272 bytes

__global__ void __launch_bounds__(512) k_hf(const float* __restrict__ pos,
                                            const float* __restrict__ wts,
                                            const float* __restrict__ W1,
                                            const float* __restrict__ b1,
                                            const float* __restrict__ cng,
                                            const float* __restrict__ cnb,
                                            const float* __restrict__ bng,
                                            const float* __restrict__ bnb,
                                            const float* __restrict__ W2,
                                            const float* __restrict__ b2,
                                            float* __restrict__ out) {
    extern __shared__ float dyn[];
    float* sxn = dyn + HF_SXN;
    float* sW1 = dyn + HF_SW1;
    float* sh  = dyn + HF_SH;
    float* sW2 = dyn + HF_SW2;
    float* sb2 = dyn + HF_SB2;
    float* sxs = dyn + HF_SXS;
    float* sxh = dyn + HF_SXH;
    float* shs = dyn + HF_SHS;
    float* shh = dyn + HF_SHH;
    float* red = dyn + HF_RED;
    int tid = threadIdx.x;
    int n0 = blockIdx.x * 64;
    if (tid < CC) {
        float mu  = g_sx[tid] * (1.f / NTOT);
        float var = fmaf(-mu, mu, g_sx2[tid] * (1.f / NTOT));
        float rsv = rsqrtf(var + 1e-5f);
        float gs  = cng[tid] * rsv;
        sxs[tid] = gs;
        sxh[tid] = fmaf(-gs, mu, cnb[tid]);
    }
    #pragma unroll
    for (int i = 0; i < 8; i++) sW1[tid + 512 * i] = W1[tid + 512 * i];
    for (int i = tid; i < CMID * 34; i += 512) sW2[i] = W2[i];
    if (tid < 34) sb2[tid] = b2[tid];
    __syncthreads();
    #pragma unroll
    for (int i = 0; i < 4; i++) {
        int idx = tid + 512 * i;
        int rr = idx >> 5, c = idx & 31;
        size_t o = (size_t)(n0 + rr) * CC + c;
        sxn[idx] = fmaf(sxs[c], g_x[o], sxh[c]) + wts[o];
    }
    __syncthreads();
    // h = leaky(xn @ W1 + b1), kept in smem; accumulate stats
    int c = tid & 127, rg = tid >> 7;   // rg 0..3
    float wreg[CC];
    #pragma unroll
    for (int cin = 0; cin < CC; cin++) wreg[cin] = sW1[cin * CMID + c];
    float bc = b1[c];
    float shsum = 0.f, sh2sum = 0.f;
    for (int i = 0; i < 16; i++) {
        int rr = rg + 4 * i;
        const float4* xr4 = (const float4*)&sxn[rr * CC];
        float a0 = bc, a1 = 0.f;
        #pragma unroll
        for (int q = 0; q < 4; q++) {
            float4 v0 = xr4[q], v1 = xr4[q + 4];
            a0 = fmaf(v0.x, wreg[4*q+0],  a0);
            a1 = fmaf(v1.x, wreg[16+4*q+0], a1);
            a0 = fmaf(v0.y, wreg[4*q+1],  a0);
            a1 = fmaf(v1.y, wreg[16+4*q+1], a1);
            a0 = fmaf(v0.z, wreg[4*q+2],  a0);
            a1 = fmaf(v1.z, wreg[16+4*q+2], a1);
            a0 = fmaf(v0.w, wreg[4*q+3],  a0);
            a1 = fmaf(v1.w, wreg[16+4*q+3], a1);
        }
        float a = a0 + a1;
        float hh = a >= 0.f ? a : 0.01f * a;
        sh[rr * CMID + c] = hh;
        shsum += hh; sh2sum += hh * hh;
    }
    red[tid] = shsum; __syncthreads();
    if (rg == 0) atomicAdd(&g_sh[c], red[c] + red[c + 128] + red[c + 256] + red[c + 384]);
    __syncthreads(); red[tid] = sh2sum; __syncthreads();
    if (rg == 0) atomicAdd(&g_sh2[c], red[c] + red[c + 128] + red[c + 256] + red[c + 384]);
    // ---- grid-wide barrier (all 128 CTAs resident) ----
    __threadfence();
    __syncthreads();
    if (tid == 0) {
        atomicAdd(&g_cnt, 1);
        while (*(volatile int*)&g_cnt < HF_GRID) { }
    }
    __syncthreads();
    __threadfence();
    // h batchnorm scales, normalize sh in place
    if (tid < CMID) {
        float mu  = g_sh[tid] * (1.f / NTOT);
        float var = fmaf(-mu, mu, g_sh2[tid] * (1.f / NTOT));
        float rsv = rsqrtf(var + 1e-5f);
        float gs  = bng[tid] * rsv;
        shs[tid] = gs;
        shh[tid] = fmaf(-gs, mu, bnb[tid]);
    }
    __syncthreads();
    #pragma unroll
    for (int i = 0; i < 16; i++) {
        int idx = tid + 512 * i;
        int cc = idx & 127;
        sh[idx] = fmaf(shs[cc], sh[idx], shh[cc]);
    }
    __syncthreads();
    // mlp_out = hn @ W2 + b2, write both outputs
    int w = tid >> 5, lane = tid & 31;
    float* out_pos = out;
    float* out_w   = out + NTOT * 2;
    #pragma unroll
    for (int r = 0; r < 4; r++) {
        int lr = w * 4 + r;
        int n  = n0 + lr;
        const float* hr = &sh[lr * CMID];
        float acc1 = sb2[lane];
        #pragma unroll 8
        for (int cin = 0; cin < CMID; cin++)
            acc1 = fmaf(hr[cin], sW2[cin * 34 + lane], acc1);
        if (lane < 2) {
            out_pos[n * 2 + lane] = pos[n * 2 + lane] + acc1;
            float acc2 = sb2[32 + lane];
            #pragma unroll 8
            for (int cin = 0; cin < CMID; cin++)
                acc2 = fmaf(hr[cin], sW2[cin * 34 + 32 + lane], acc2);
            out_w[n * CC + 30 + lane] = sxn[lr * CC + 30 + lane] + acc2;
        } else {
            out_w[n * CC + lane - 2] = sxn[lr * CC + lane - 2] + acc1;
        }
    }
}

// ---------------- launch ----------------------------------------------------
extern "C" void kernel_launch(void* const* d_in, const int* in_sizes, int n_in,
                              void* d_out, int out_size) {
    const float* positions = (const float*)d_in[0];
    const float* weights   = (const float*)d_in[1];
    const float* kpos = (const float*)d_in[3];
    const float* kw   = (const float*)d_in[4];
    const float* cng  = (const float*)d_in[5];
    const float* cnb  = (const float*)d_in[6];
    const float* W1   = (const float*)d_in[7];
    const float* b1   = (const float*)d_in[8];
    const float* bng  = (const float*)d_in[9];
    const float* bnb  = (const float*)d_in[10];
    const float* W2   = (const float*)d_in[11];
    const float* b2   = (const float*)d_in[12];
    float* out = (float*)d_out;

    cudaFuncSetAttribute(k_hf, cudaFuncAttributeMaxDynamicSharedMemorySize,
                         HF_FLOATS * 4);
    k_prep<<<512, 288>>>(positions, weights, kpos, kw);
    k_main<<<144, 512>>>(positions);
    k_hf<<<HF_GRID, 512, HF_FLOATS * 4>>>(positions, weights, W1, b1,
                                          cng, cnb, bng, bnb, W2, b2, out);
}

// round 10
// speedup vs baseline: 1.2185x; 1.2185x over previous
#include <cuda_runtime.h>
#include <cuda_fp16.h>
#include <cstdint>

#define NTOT 8192
#define BB   8
#define NBAT 1024
#define KK   9
#define CC   32
#define CMID 128
#define MM   9216        // NBAT*KK per batch
#define KSPLIT 9
#define KPART  1024      // MM / KSPLIT
#define NCH    32        // KPART / 32
#define NGRP   16        // b(8) x rowblock(2)
#define HF_GRID 128

// ---------------- scratch (device globals; no allocation anywhere) ----------
__device__ __half  g_convwT[BB * CC * MM];  // [b][c][m], fp16
__device__ float4  g_abxy[BB * MM];         // (am, bx, by, 0) per m
__device__ float   g_part[KSPLIT * NTOT * CC];
__device__ float   g_x[NTOT * CC];          // leaky(sampled)
__device__ float   g_sx[CC], g_sx2[CC], g_sh[CMID], g_sh2[CMID];
__device__ int     g_sync[NGRP];            // k_main group counters
__device__ int     g_cnt;                   // k_hf barrier counter

// ---------------- helpers ----------------------------------------------------
// pack two fp32 args to f16x2 (lo, hi) and take 2^x of both in one MUFU op
__device__ __forceinline__ uint32_t ex2h2(float lo, float hi) {
    uint32_t h2, r;
    asm("cvt.rn.f16x2.f32 %0, %1, %2;" : "=r"(h2) : "f"(hi), "f"(lo));
    asm("ex2.approx.f16x2 %0, %1;" : "=r"(r) : "r"(h2));
    return r;
}
__device__ __forceinline__ void mma_f16(float* d,
                                        uint32_t a0, uint32_t a1,
                                        uint32_t a2, uint32_t a3,
                                        uint32_t b0, uint32_t b1) {
    asm volatile(
        "mma.sync.aligned.m16n8k16.row.col.f32.f16.f16.f32 "
        "{%0,%1,%2,%3}, {%4,%5,%6,%7}, {%8,%9}, {%0,%1,%2,%3};"
        : "+f"(d[0]), "+f"(d[1]), "+f"(d[2]), "+f"(d[3])
        : "r"(a0), "r"(a1), "r"(a2), "r"(a3), "r"(b0), "r"(b1));
}

#define LOG2E 1.4426950408889634f
#define C2    (-2.0f * LOG2E)

// ---------------- K1: conv_w^T (fp16) + abxy + zero counters ----------------
// grid 256 (32 n per block), 288 threads = (k=tid/32, d=tid%32)
// (Round-7 structure: best measured config for this kernel.)
__global__ void __launch_bounds__(288) k_prep(const float* __restrict__ pos,
                                              const float* __restrict__ wts,
                                              const float* __restrict__ kpos,
                                              const float* __restrict__ kw) {
    __shared__ __align__(16) float sw[32 * CC];       // 4 KB
    __shared__ float sp[64];
    __shared__ float skp[KK * 2];
    __shared__ float st[32 * KK * 33];                // 38 KB, [m_local][d] pad33
    int tid = threadIdx.x;
    int n0 = blockIdx.x * 32;          // global n
    int b  = n0 >> 10;
    int m0 = (n0 & 1023) * KK;         // m within batch
    if (blockIdx.x == 0) {             // re-zero per replay
        if (tid < CC)   { g_sx[tid] = 0.f; g_sx2[tid] = 0.f; }
        if (tid < CMID) { g_sh[tid] = 0.f; g_sh2[tid] = 0.f; }
        if (tid < NGRP) g_sync[tid] = 0;
        if (tid == NGRP) g_cnt = 0;
    }
    for (int i = tid; i < 32 * CC; i += 288) sw[i] = wts[n0 * CC + i];
    if (tid < 64) sp[tid] = pos[n0 * 2 + tid];
    if (tid < KK * 2) skp[tid] = kpos[tid];
    int k = tid / 32, d = tid % 32;
    float kr[CC];
    #pragma unroll
    for (int c = 0; c < CC; c++) kr[c] = kw[(k * CC + c) * CC + d];
    __syncthreads();
    #pragma unroll 4
    for (int n = 0; n < 32; n++) {
        const float4* swr = (const float4*)(sw + n * CC);
        float a = 0.f;
        #pragma unroll
        for (int q = 0; q < 8; q++) {
            float4 v = swr[q];
            a = fmaf(v.x, kr[4*q+0], a);
            a = fmaf(v.y, kr[4*q+1], a);
            a = fmaf(v.z, kr[4*q+2], a);
            a = fmaf(v.w, kr[4*q+3], a);
        }
        st[(n * KK + k) * 33 + d] = a;
    }
    // abxy (288 m's, one per thread)
    {
        int n = tid / KK, kk = tid % KK;
        float cpx = sp[2 * n]     + skp[2 * kk];
        float cpy = sp[2 * n + 1] + skp[2 * kk + 1];
        float am  = C2 * fmaf(cpx, cpx, cpy * cpy);
        g_abxy[(size_t)b * MM + m0 + tid] =
            make_float4(am, 4.f * LOG2E * cpx, 4.f * LOG2E * cpy, 0.f);
    }
    __syncthreads();
    // transposed writeout: warp wi handles (c,j) pairs, lane covers 32 m's
    {
        int wi = tid >> 5, lane = tid & 31;
        for (int it = 0; it < 32; it++) {
            int cj = wi + 9 * it;        // 0..287
            int c = cj / KK, j = cj - c * KK;
            float v = st[(j * 32 + lane) * 33 + c];   // bank (lane+c)%32, CF
            g_convwT[((size_t)b * CC + c) * MM + m0 + j * 32 + lane] =
                __float2half_rn(v);
        }
    }
}

// ---------------- K2: Kmat @ conv_w via mma.sync fp16 (m16n8k16) ------------
// grid 144 = b(8) x rowblock(2) x ksplit(9); 512 threads = 16 warps,
// each warp owns a 32x32 output tile. A generated in registers via
// ex2.approx.f16x2 (2 exps / MUFU op). B staged as fp16, row stride 20 words
// (bank-conflict-free fragment reads).
__global__ void __launch_bounds__(512) k_main(const float* __restrict__ pos) {
    __shared__ uint32_t sB[2][32 * 20]; // fp16 tiles, 2.5 KB each
    __shared__ float4   sAB[2][32];
    __shared__ float    red[512];
    __shared__ int      s_last;
    int tid  = threadIdx.x;
    int w    = tid >> 5, lane = tid & 31;
    int g    = lane >> 2, t = lane & 3;
    int blk  = blockIdx.x;
    int b   = blk / 18;
    int rem = blk - b * 18;
    int rb  = rem / 9;
    int ks  = rem - rb * 9;
    int ctabase = b * NBAT + rb * 512;
    int rbase   = ctabase + w * 32;
    size_t mbase = (size_t)b * MM + (size_t)ks * KPART;

    // staging mapping: threads 0..255 -> (c = tid>>3, q = tid&7), uint2/chunk
    int sc = tid >> 3, sq = tid & 7;
    const uint2* gB = (const uint2*)(g_convwT + ((size_t)b * CC + sc) * MM
                                     + (size_t)ks * KPART);
    const float4* gAB = g_abxy + mbase;

    // per-lane row data: rows rbase + g + 8u, u = 0..3
    float px[4], py[4], pp[4];
    #pragma unroll
    for (int u = 0; u < 4; u++) {
        float2 p = ((const float2*)pos)[rbase + g + 8 * u];
        px[u] = p.x; py[u] = p.y;
        pp[u] = C2 * fmaf(p.x, p.x, p.y * p.y);
    }
    float acc[2][4][4];
    #pragma unroll
    for (int j = 0; j < 2; j++)
        #pragma unroll
        for (int i = 0; i < 4; i++)
            #pragma unroll
            for (int q = 0; q < 4; q++) acc[j][i][q] = 0.f;

    // stage chunk 0
    if (tid < 256) {
        uint2 v = gB[sq];
        sB[0][sc * 20 + sq * 2]     = v.x;
        sB[0][sc * 20 + sq * 2 + 1] = v.y;
    }
    if (tid < 32) sAB[0][tid] = gAB[tid];
    for (int tc = 0; tc < NCH; tc++) {
        int buf = tc & 1;
        __syncthreads();
        if (tc + 1 < NCH) {
            if (tid < 256) {
                uint2 v = gB[(tc + 1) * 8 + sq];
                sB[buf ^ 1][sc * 20 + sq * 2]     = v.x;
                sB[buf ^ 1][sc * 20 + sq * 2 + 1] = v.y;
            }
            if (tid < 32) sAB[buf ^ 1][tid] = gAB[(tc + 1) * 32 + tid];
        }
        // A fragments: A16[u][v] = f16x2 of K rows (g+8u), m = (2t+8v, 2t+8v+1)
        uint32_t A16[4][4];
        #pragma unroll
        for (int v = 0; v < 4; v++) {
            float4 qa = sAB[buf][2 * t + 8 * v];
            float4 qb = sAB[buf][2 * t + 8 * v + 1];
            #pragma unroll
            for (int u = 0; u < 4; u++) {
                float lo = fmaf(qa.y, px[u], fmaf(qa.z, py[u], pp[u] + qa.x));
                float hi = fmaf(qb.y, px[u], fmaf(qb.z, py[u], pp[u] + qb.x));
                A16[u][v] = ex2h2(lo, hi);
            }
        }
        // MMAs: 2 j-tiles x 4 i-tiles x 2 k16-steps
        #pragma unroll
        for (int i = 0; i < 4; i++) {
            int base = (i * 8 + g) * 20;
            #pragma unroll
            for (int s = 0; s < 2; s++) {
                uint32_t b0 = sB[buf][base + 8 * s + t];
                uint32_t b1 = sB[buf][base + 8 * s + t + 4];
                #pragma unroll
                for (int j = 0; j < 2; j++)
                    mma_f16(acc[j][i],
                            A16[2*j][2*s],   A16[2*j+1][2*s],
                            A16[2*j][2*s+1], A16[2*j+1][2*s+1],
                            b0, b1);
            }
        }
    }
    // store partials: frag (j,i): rows rbase+j*16+g (+8), cols i*8+t*2 (+1)
    #pragma unroll
    for (int j = 0; j < 2; j++) {
        int nr0 = rbase + j * 16 + g;
        #pragma unroll
        for (int i = 0; i < 4; i++) {
            int c = i * 8 + t * 2;
            *(float2*)&g_part[((size_t)ks * NTOT + nr0) * CC + c] =
                make_float2(acc[j][i][0], acc[j][i][1]);
            *(float2*)&g_part[((size_t)ks * NTOT + nr0 + 8) * CC + c] =
                make_float2(acc[j][i][2], acc[j][i][3]);
        }
    }
    // ---- group finish: last CTA reduces ----
    __threadfence();
    __syncthreads();
    if (tid == 0) s_last = (atomicAdd(&g_sync[b * 2 + rb], 1) == KSPLIT - 1);
    __syncthreads();
    if (!s_last) return;
    __threadfence();
    int c = tid & 31, rs = tid >> 5;    // rs 0..15
    float sx = 0.f, sx2 = 0.f;
    for (int i = 0; i < 32; i++) {
        int n = ctabase + i * 16 + rs;
        size_t o = (size_t)n * CC + c;
        float v = 0.f;
        #pragma unroll
        for (int s = 0; s < KSPLIT; s++) v += g_part[(size_t)s * NTOT * CC + o];
        float x = v >= 0.f ? v : 0.01f * v;
        g_x[o] = x;
        sx += x; sx2 += x * x;
    }
    red[tid] = sx; __syncthreads();
    if (rs == 0) {
        float s = 0.f;
        #pragma unroll
        for (int j = 0; j < 16; j++) s += red[c + 32 * j];
        atomicAdd(&g_sx[c], s);
    }
    __syncthreads(); red[tid] = sx2; __syncthreads();
    if (rs == 0) {
        float s = 0.f;
        #pragma unroll
        for (int j = 0; j < 16; j++) s += red[c + 32 * j];
        atomicAdd(&g_sx2[c], s);
    }
}

// ---------------- K3: fused  xn -> h -> BN(h) -> W2 -> outputs --------------
// grid 128, 512 threads; 64 rows/block; grid-wide spin barrier (all resident).
#define HF_SXN  0        // 64*32   = 2048
#define HF_SW1  2048     // 32*128  = 4096
#define HF_SH   6144     // 64*128  = 8192
#define HF_SW2  14336    // 128*34  = 4352
#define HF_SB2  18688    // 48
#define HF_SXS  18736    // 32
#define HF_SXH  18768    // 32
#define HF_SHS  18800    // 128
#define HF_SHH  18928    // 128
#define HF_RED  19056    // 512
#define HF_FLOATS 19568  // 78272 bytes

__global__ void __launch_bounds__(512) k_hf(const float* __restrict__ pos,
                                            const float* __restrict__ wts,
                                            const float* __restrict__ W1,
                                            const float* __restrict__ b1,
                                            const float* __restrict__ cng,
                                            const float* __restrict__ cnb,
                                            const float* __restrict__ bng,
                                            const float* __restrict__ bnb,
                                            const float* __restrict__ W2,
                                            const float* __restrict__ b2,
                                            float* __restrict__ out) {
    extern __shared__ float dyn[];
    float* sxn = dyn + HF_SXN;
    float* sW1 = dyn + HF_SW1;
    float* sh  = dyn + HF_SH;
    float* sW2 = dyn + HF_SW2;
    float* sb2 = dyn + HF_SB2;
    float* sxs = dyn + HF_SXS;
    float* sxh = dyn + HF_SXH;
    float* shs = dyn + HF_SHS;
    float* shh = dyn + HF_SHH;
    float* red = dyn + HF_RED;
    int tid = threadIdx.x;
    int n0 = blockIdx.x * 64;
    if (tid < CC) {
        float mu  = g_sx[tid] * (1.f / NTOT);
        float var = fmaf(-mu, mu, g_sx2[tid] * (1.f / NTOT));
        float rsv = rsqrtf(var + 1e-5f);
        float gs  = cng[tid] * rsv;
        sxs[tid] = gs;
        sxh[tid] = fmaf(-gs, mu, cnb[tid]);
    }
    #pragma unroll
    for (int i = 0; i < 8; i++) sW1[tid + 512 * i] = W1[tid + 512 * i];
    for (int i = tid; i < CMID * 34; i += 512) sW2[i] = W2[i];
    if (tid < 34) sb2[tid] = b2[tid];
    __syncthreads();
    #pragma unroll
    for (int i = 0; i < 4; i++) {
        int idx = tid + 512 * i;
        int rr = idx >> 5, c = idx & 31;
        size_t o = (size_t)(n0 + rr) * CC + c;
        sxn[idx] = fmaf(sxs[c], g_x[o], sxh[c]) + wts[o];
    }
    __syncthreads();
    int c = tid & 127, rg = tid >> 7;   // rg 0..3
    float wreg[CC];
    #pragma unroll
    for (int cin = 0; cin < CC; cin++) wreg[cin] = sW1[cin * CMID + c];
    float bc = b1[c];
    float shsum = 0.f, sh2sum = 0.f;
    for (int i = 0; i < 16; i++) {
        int rr = rg + 4 * i;
        const float4* xr4 = (const float4*)&sxn[rr * CC];
        float a0 = bc, a1 = 0.f;
        #pragma unroll
        for (int q = 0; q < 4; q++) {
            float4 v0 = xr4[q], v1 = xr4[q + 4];
            a0 = fmaf(v0.x, wreg[4*q+0],  a0);
            a1 = fmaf(v1.x, wreg[16+4*q+0], a1);
            a0 = fmaf(v0.y, wreg[4*q+1],  a0);
            a1 = fmaf(v1.y, wreg[16+4*q+1], a1);
            a0 = fmaf(v0.z, wreg[4*q+2],  a0);
            a1 = fmaf(v1.z, wreg[16+4*q+2], a1);
            a0 = fmaf(v0.w, wreg[4*q+3],  a0);
            a1 = fmaf(v1.w, wreg[16+4*q+3], a1);
        }
        float a = a0 + a1;
        float hh = a >= 0.f ? a : 0.01f * a;
        sh[rr * CMID + c] = hh;
        shsum += hh; sh2sum += hh * hh;
    }
    red[tid] = shsum; __syncthreads();
    if (rg == 0) atomicAdd(&g_sh[c], red[c] + red[c + 128] + red[c + 256] + red[c + 384]);
    __syncthreads(); red[tid] = sh2sum; __syncthreads();
    if (rg == 0) atomicAdd(&g_sh2[c], red[c] + red[c + 128] + red[c + 256] + red[c + 384]);
    // ---- grid-wide barrier (all 128 CTAs resident) ----
    __threadfence();
    __syncthreads();
    if (tid == 0) {
        atomicAdd(&g_cnt, 1);
        while (*(volatile int*)&g_cnt < HF_GRID) { }
    }
    __syncthreads();
    __threadfence();
    if (tid < CMID) {
        float mu  = g_sh[tid] * (1.f / NTOT);
        float var = fmaf(-mu, mu, g_sh2[tid] * (1.f / NTOT));
        float rsv = rsqrtf(var + 1e-5f);
        float gs  = bng[tid] * rsv;
        shs[tid] = gs;
        shh[tid] = fmaf(-gs, mu, bnb[tid]);
    }
    __syncthreads();
    #pragma unroll
    for (int i = 0; i < 16; i++) {
        int idx = tid + 512 * i;
        int cc = idx & 127;
        sh[idx] = fmaf(shs[cc], sh[idx], shh[cc]);
    }
    __syncthreads();
    int w = tid >> 5, lane = tid & 31;
    float* out_pos = out;
    float* out_w   = out + NTOT * 2;
    #pragma unroll
    for (int r = 0; r < 4; r++) {
        int lr = w * 4 + r;
        int n  = n0 + lr;
        const float* hr = &sh[lr * CMID];
        float acc1 = sb2[lane];
        #pragma unroll 8
        for (int cin = 0; cin < CMID; cin++)
            acc1 = fmaf(hr[cin], sW2[cin * 34 + lane], acc1);
        if (lane < 2) {
            out_pos[n * 2 + lane] = pos[n * 2 + lane] + acc1;
            float acc2 = sb2[32 + lane];
            #pragma unroll 8
            for (int cin = 0; cin < CMID; cin++)
                acc2 = fmaf(hr[cin], sW2[cin * 34 + 32 + lane], acc2);
            out_w[n * CC + 30 + lane] = sxn[lr * CC + 30 + lane] + acc2;
        } else {
            out_w[n * CC + lane - 2] = sxn[lr * CC + lane - 2] + acc1;
        }
    }
}

// ---------------- launch ----------------------------------------------------
extern "C" void kernel_launch(void* const* d_in, const int* in_sizes, int n_in,
                              void* d_out, int out_size) {
    const float* positions = (const float*)d_in[0];
    const float* weights   = (const float*)d_in[1];
    const float* kpos = (const float*)d_in[3];
    const float* kw   = (const float*)d_in[4];
    const float* cng  = (const float*)d_in[5];
    const float* cnb  = (const float*)d_in[6];
    const float* W1   = (const float*)d_in[7];
    const float* b1   = (const float*)d_in[8];
    const float* bng  = (const float*)d_in[9];
    const float* bnb  = (const float*)d_in[10];
    const float* W2   = (const float*)d_in[11];
    const float* b2   = (const float*)d_in[12];
    float* out = (float*)d_out;

    cudaFuncSetAttribute(k_hf, cudaFuncAttributeMaxDynamicSharedMemorySize,
                         HF_FLOATS * 4);
    k_prep<<<256, 288>>>(positions, weights, kpos, kw);
    k_main<<<144, 512>>>(positions);
    k_hf<<<HF_GRID, 512, HF_FLOATS * 4>>>(positions, weights, W1, b1,
                                          cng, cnb, bng, bnb, W2, b2, out);
}

// round 11
// speedup vs baseline: 1.2734x; 1.0450x over previous
#include <cuda_runtime.h>
#include <cuda_fp16.h>
#include <cstdint>

#define NTOT 8192
#define BB   8
#define NBAT 1024
#define KK   9
#define CC   32
#define CMID 128
#define MM   9216        // NBAT*KK per batch
#define KSPLIT 9
#define KPART  1024      // MM / KSPLIT
#define NCH    32        // KPART / 32
#define HF_GRID 128
#define PG     16        // n per k_prep block
#define PM     (PG * KK) // 144 m per k_prep block

// ---------------- scratch (device globals; no allocation anywhere) ----------
__device__ __half  g_convwT[BB * CC * MM];  // [b][c][m], fp16
__device__ float4  g_abxy[BB * MM];         // (am, bx, by, 0) per m
__device__ float   g_part[KSPLIT * NTOT * CC];
__device__ float   g_sx[CC], g_sx2[CC], g_sh[CMID], g_sh2[CMID];
__device__ int     g_cntx;                  // k_hf barrier 0 counter
__device__ int     g_cnth;                  // k_hf barrier 1 counter

// ---------------- helpers ----------------------------------------------------
__device__ __forceinline__ uint32_t ex2h2(float lo, float hi) {
    uint32_t h2, r;
    asm("cvt.rn.f16x2.f32 %0, %1, %2;" : "=r"(h2) : "f"(hi), "f"(lo));
    asm("ex2.approx.f16x2 %0, %1;" : "=r"(r) : "r"(h2));
    return r;
}
__device__ __forceinline__ void mma_f16(float* d,
                                        uint32_t a0, uint32_t a1,
                                        uint32_t a2, uint32_t a3,
                                        uint32_t b0, uint32_t b1) {
    asm volatile(
        "mma.sync.aligned.m16n8k16.row.col.f32.f16.f16.f32 "
        "{%0,%1,%2,%3}, {%4,%5,%6,%7}, {%8,%9}, {%0,%1,%2,%3};"
        : "+f"(d[0]), "+f"(d[1]), "+f"(d[2]), "+f"(d[3])
        : "r"(a0), "r"(a1), "r"(a2), "r"(a3), "r"(b0), "r"(b1));
}

#define LOG2E 1.4426950408889634f
#define C2    (-2.0f * LOG2E)

// ---------------- K1: conv_w^T (fp16) + abxy + zero counters ----------------
// grid 512 (16 n per block), 288 threads = (k=tid/32, d=tid%32)
// Same serial einsum / writeout structure as the measured 12.9us version;
// only the per-block n-tile is halved to double occupancy.
__global__ void __launch_bounds__(288) k_prep(const float* __restrict__ pos,
                                              const float* __restrict__ wts,
                                              const float* __restrict__ kpos,
                                              const float* __restrict__ kw) {
    __shared__ __align__(16) float sw[PG * CC];       // 2 KB
    __shared__ float sp[PG * 2];
    __shared__ float skp[KK * 2];
    __shared__ float st[PM * 33];                     // 19 KB, [m_local][d] pad33
    int tid = threadIdx.x;
    int n0 = blockIdx.x * PG;          // global n
    int b  = n0 >> 10;
    int m0 = (n0 & 1023) * KK;         // m within batch
    if (blockIdx.x == 0) {             // re-zero per replay
        if (tid < CC)   { g_sx[tid] = 0.f; g_sx2[tid] = 0.f; }
        if (tid < CMID) { g_sh[tid] = 0.f; g_sh2[tid] = 0.f; }
        if (tid == CMID)     g_cntx = 0;
        if (tid == CMID + 1) g_cnth = 0;
    }
    for (int i = tid; i < PG * CC; i += 288) sw[i] = wts[n0 * CC + i];
    if (tid < PG * 2) sp[tid] = pos[n0 * 2 + tid];
    if (tid < KK * 2) skp[tid] = kpos[tid];
    int k = tid / 32, d = tid % 32;
    float kr[CC];
    #pragma unroll
    for (int c = 0; c < CC; c++) kr[c] = kw[(k * CC + c) * CC + d];
    __syncthreads();
    #pragma unroll 4
    for (int n = 0; n < PG; n++) {
        const float4* swr = (const float4*)(sw + n * CC);
        float a = 0.f;
        #pragma unroll
        for (int q = 0; q < 8; q++) {
            float4 v = swr[q];
            a = fmaf(v.x, kr[4*q+0], a);
            a = fmaf(v.y, kr[4*q+1], a);
            a = fmaf(v.z, kr[4*q+2], a);
            a = fmaf(v.w, kr[4*q+3], a);
        }
        st[(n * KK + k) * 33 + d] = a;
    }
    // abxy (144 m's, one per thread)
    if (tid < PM) {
        int n = tid / KK, kk = tid - (tid / KK) * KK;
        float cpx = sp[2 * n]     + skp[2 * kk];
        float cpy = sp[2 * n + 1] + skp[2 * kk + 1];
        float am  = C2 * fmaf(cpx, cpx, cpy * cpy);
        g_abxy[(size_t)b * MM + m0 + tid] =
            make_float4(am, 4.f * LOG2E * cpx, 4.f * LOG2E * cpy, 0.f);
    }
    __syncthreads();
    // transposed writeout: idx = c*144 + mm; consecutive threads -> consecutive
    // mm -> contiguous halfs; LDS bank (mm+c)%32 conflict-free.
    #pragma unroll
    for (int it = 0; it < PM * CC / 288; it++) {
        int idx = tid + it * 288;
        int c  = idx / PM;
        int mm = idx - c * PM;
        g_convwT[((size_t)b * CC + c) * MM + m0 + mm] =
            __float2half_rn(st[mm * 33 + c]);
    }
}

// ---------------- K2: Kmat @ conv_w via mma.sync fp16 (m16n8k16) ------------
// grid 144 = b(8) x rowblock(2) x ksplit(9); 512 threads = 16 warps,
// each warp owns a 32x32 output tile. Pure GEMM: partials written, no epilogue.
__global__ void __launch_bounds__(512) k_main(const float* __restrict__ pos) {
    __shared__ uint32_t sB[2][32 * 20]; // fp16 tiles, 2.5 KB each
    __shared__ float4   sAB[2][32];
    int tid  = threadIdx.x;
    int w    = tid >> 5, lane = tid & 31;
    int g    = lane >> 2, t = lane & 3;
    int blk  = blockIdx.x;
    int b   = blk / 18;
    int rem = blk - b * 18;
    int rb  = rem / 9;
    int ks  = rem - rb * 9;
    int ctabase = b * NBAT + rb * 512;
    int rbase   = ctabase + w * 32;
    size_t mbase = (size_t)b * MM + (size_t)ks * KPART;

    int sc = tid >> 3, sq = tid & 7;
    const uint2* gB = (const uint2*)(g_convwT + ((size_t)b * CC + sc) * MM
                                     + (size_t)ks * KPART);
    const float4* gAB = g_abxy + mbase;

    float px[4], py[4], pp[4];
    #pragma unroll
    for (int u = 0; u < 4; u++) {
        float2 p = ((const float2*)pos)[rbase + g + 8 * u];
        px[u] = p.x; py[u] = p.y;
        pp[u] = C2 * fmaf(p.x, p.x, p.y * p.y);
    }
    float acc[2][4][4];
    #pragma unroll
    for (int j = 0; j < 2; j++)
        #pragma unroll
        for (int i = 0; i < 4; i++)
            #pragma unroll
            for (int q = 0; q < 4; q++) acc[j][i][q] = 0.f;

    if (tid < 256) {
        uint2 v = gB[sq];
        sB[0][sc * 20 + sq * 2]     = v.x;
        sB[0][sc * 20 + sq * 2 + 1] = v.y;
    }
    if (tid < 32) sAB[0][tid] = gAB[tid];
    for (int tc = 0; tc < NCH; tc++) {
        int buf = tc & 1;
        __syncthreads();
        if (tc + 1 < NCH) {
            if (tid < 256) {
                uint2 v = gB[(tc + 1) * 8 + sq];
                sB[buf ^ 1][sc * 20 + sq * 2]     = v.x;
                sB[buf ^ 1][sc * 20 + sq * 2 + 1] = v.y;
            }
            if (tid < 32) sAB[buf ^ 1][tid] = gAB[(tc + 1) * 32 + tid];
        }
        uint32_t A16[4][4];
        #pragma unroll
        for (int v = 0; v < 4; v++) {
            float4 qa = sAB[buf][2 * t + 8 * v];
            float4 qb = sAB[buf][2 * t + 8 * v + 1];
            #pragma unroll
            for (int u = 0; u < 4; u++) {
                float lo = fmaf(qa.y, px[u], fmaf(qa.z, py[u], pp[u] + qa.x));
                float hi = fmaf(qb.y, px[u], fmaf(qb.z, py[u], pp[u] + qb.x));
                A16[u][v] = ex2h2(lo, hi);
            }
        }
        #pragma unroll
        for (int i = 0; i < 4; i++) {
            int base = (i * 8 + g) * 20;
            #pragma unroll
            for (int s = 0; s < 2; s++) {
                uint32_t b0 = sB[buf][base + 8 * s + t];
                uint32_t b1 = sB[buf][base + 8 * s + t + 4];
                #pragma unroll
                for (int j = 0; j < 2; j++)
                    mma_f16(acc[j][i],
                            A16[2*j][2*s],   A16[2*j+1][2*s],
                            A16[2*j][2*s+1], A16[2*j+1][2*s+1],
                            b0, b1);
            }
        }
    }
    #pragma unroll
    for (int j = 0; j < 2; j++) {
        int nr0 = rbase + j * 16 + g;
        #pragma unroll
        for (int i = 0; i < 4; i++) {
            int c = i * 8 + t * 2;
            *(float2*)&g_part[((size_t)ks * NTOT + nr0) * CC + c] =
                make_float2(acc[j][i][0], acc[j][i][1]);
            *(float2*)&g_part[((size_t)ks * NTOT + nr0 + 8) * CC + c] =
                make_float2(acc[j][i][2], acc[j][i][3]);
        }
    }
}

// ---------------- K3: reduce -> x-stats -> xn -> h -> BN(h) -> W2 -> out ----
// grid 128, 512 threads; 64 rows/block; TWO grid-wide spin barriers
// (128 CTAs all resident).
#define HF_SXN  0        // 64*32   = 2048
#define HF_SW1  2048     // 32*128  = 4096
#define HF_SH   6144     // 64*128  = 8192
#define HF_SW2  14336    // 128*34  = 4352
#define HF_SB2  18688    // 48
#define HF_SXS  18736    // 32
#define HF_SXH  18768    // 32
#define HF_SHS  18800    // 128
#define HF_SHH  18928    // 128
#define HF_RED  19056    // 512
#define HF_FLOATS 19568  // 78272 bytes

__global__ void __launch_bounds__(512) k_hf(const float* __restrict__ pos,
                                            const float* __restrict__ wts,
                                            const float* __restrict__ W1,
                                            const float* __restrict__ b1,
                                            const float* __restrict__ cng,
                                            const float* __restrict__ cnb,
                                            const float* __restrict__ bng,
                                            const float* __restrict__ bnb,
                                            const float* __restrict__ W2,
                                            const float* __restrict__ b2,
                                            float* __restrict__ out) {
    extern __shared__ float dyn[];
    float* sxn = dyn + HF_SXN;
    float* sW1 = dyn + HF_SW1;
    float* sh  = dyn + HF_SH;
    float* sW2 = dyn + HF_SW2;
    float* sb2 = dyn + HF_SB2;
    float* sxs = dyn + HF_SXS;
    float* sxh = dyn + HF_SXH;
    float* shs = dyn + HF_SHS;
    float* shh = dyn + HF_SHH;
    float* red = dyn + HF_RED;
    int tid = threadIdx.x;
    int n0 = blockIdx.x * 64;
    // weight staging (overlaps phase 0)
    #pragma unroll
    for (int i = 0; i < 8; i++) sW1[tid + 512 * i] = W1[tid + 512 * i];
    for (int i = tid; i < CMID * 34; i += 512) sW2[i] = W2[i];
    if (tid < 34) sb2[tid] = b2[tid];
    // ---- phase 0: reduce KSPLIT partials, leaky, local x into smem ----
    {
        int n = tid >> 3, c4 = (tid & 7) * 4;
        const float4* base = (const float4*)(g_part
                              + (size_t)(n0 + n) * CC + c4);
        float4 a = base[0];
        #pragma unroll
        for (int s = 1; s < KSPLIT; s++) {
            float4 v = base[(size_t)s * (NTOT * CC / 4)];
            a.x += v.x; a.y += v.y; a.z += v.z; a.w += v.w;
        }
        a.x = a.x >= 0.f ? a.x : 0.01f * a.x;
        a.y = a.y >= 0.f ? a.y : 0.01f * a.y;
        a.z = a.z >= 0.f ? a.z : 0.01f * a.z;
        a.w = a.w >= 0.f ? a.w : 0.01f * a.w;
        *(float4*)&sxn[n * CC + c4] = a;
    }
    __syncthreads();
    // x-stats over this CTA's 64 rows
    {
        int c = tid & 31, rs = tid >> 5;   // rs 0..15
        float sx = 0.f, sx2 = 0.f;
        #pragma unroll
        for (int i = 0; i < 4; i++) {
            float v = sxn[(rs + 16 * i) * CC + c];
            sx += v; sx2 += v * v;
        }
        red[tid] = sx; __syncthreads();
        if (rs == 0) {
            float s = 0.f;
            #pragma unroll
            for (int j = 0; j < 16; j++) s += red[c + 32 * j];
            atomicAdd(&g_sx[c], s);
        }
        __syncthreads(); red[tid] = sx2; __syncthreads();
        if (rs == 0) {
            float s = 0.f;
            #pragma unroll
            for (int j = 0; j < 16; j++) s += red[c + 32 * j];
            atomicAdd(&g_sx2[c], s);
        }
    }
    // ---- barrier 0: x-stats complete chip-wide ----
    __threadfence();
    __syncthreads();
    if (tid == 0) {
        atomicAdd(&g_cntx, 1);
        while (*(volatile int*)&g_cntx < HF_GRID) { }
    }
    __syncthreads();
    __threadfence();
    if (tid < CC) {
        float mu  = g_sx[tid] * (1.f / NTOT);
        float var = fmaf(-mu, mu, g_sx2[tid] * (1.f / NTOT));
        float rsv = rsqrtf(var + 1e-5f);
        float gs  = cng[tid] * rsv;
        sxs[tid] = gs;
        sxh[tid] = fmaf(-gs, mu, cnb[tid]);
    }
    __syncthreads();
    // xn in place
    #pragma unroll
    for (int i = 0; i < 4; i++) {
        int idx = tid + 512 * i;
        int rr = idx >> 5, c = idx & 31;
        sxn[idx] = fmaf(sxs[c], sxn[idx], sxh[c])
                   + wts[(size_t)(n0 + rr) * CC + c];
    }
    __syncthreads();
    // h = leaky(xn @ W1 + b1), kept in smem; accumulate stats
    int c = tid & 127, rg = tid >> 7;   // rg 0..3
    float wreg[CC];
    #pragma unroll
    for (int cin = 0; cin < CC; cin++) wreg[cin] = sW1[cin * CMID + c];
    float bc = b1[c];
    float shsum = 0.f, sh2sum = 0.f;
    for (int i = 0; i < 16; i++) {
        int rr = rg + 4 * i;
        const float4* xr4 = (const float4*)&sxn[rr * CC];
        float a0 = bc, a1 = 0.f;
        #pragma unroll
        for (int q = 0; q < 4; q++) {
            float4 v0 = xr4[q], v1 = xr4[q + 4];
            a0 = fmaf(v0.x, wreg[4*q+0],  a0);
            a1 = fmaf(v1.x, wreg[16+4*q+0], a1);
            a0 = fmaf(v0.y, wreg[4*q+1],  a0);
            a1 = fmaf(v1.y, wreg[16+4*q+1], a1);
            a0 = fmaf(v0.z, wreg[4*q+2],  a0);
            a1 = fmaf(v1.z, wreg[16+4*q+2], a1);
            a0 = fmaf(v0.w, wreg[4*q+3],  a0);
            a1 = fmaf(v1.w, wreg[16+4*q+3], a1);
        }
        float a = a0 + a1;
        float hh = a >= 0.f ? a : 0.01f * a;
        sh[rr * CMID + c] = hh;
        shsum += hh; sh2sum += hh * hh;
    }
    red[tid] = shsum; __syncthreads();
    if (rg == 0) atomicAdd(&g_sh[c], red[c] + red[c + 128] + red[c + 256] + red[c + 384]);
    __syncthreads(); red[tid] = sh2sum; __syncthreads();
    if (rg == 0) atomicAdd(&g_sh2[c], red[c] + red[c + 128] + red[c + 256] + red[c + 384]);
    // ---- barrier 1: h-stats complete chip-wide ----
    __threadfence();
    __syncthreads();
    if (tid == 0) {
        atomicAdd(&g_cnth, 1);
        while (*(volatile int*)&g_cnth < HF_GRID) { }
    }
    __syncthreads();
    __threadfence();
    if (tid < CMID) {
        float mu  = g_sh[tid] * (1.f / NTOT);
        float var = fmaf(-mu, mu, g_sh2[tid] * (1.f / NTOT));
        float rsv = rsqrtf(var + 1e-5f);
        float gs  = bng[tid] * rsv;
        shs[tid] = gs;
        shh[tid] = fmaf(-gs, mu, bnb[tid]);
    }
    __syncthreads();
    #pragma unroll
    for (int i = 0; i < 16; i++) {
        int idx = tid + 512 * i;
        int cc = idx & 127;
        sh[idx] = fmaf(shs[cc], sh[idx], shh[cc]);
    }
    __syncthreads();
    int w = tid >> 5, lane = tid & 31;
    float* out_pos = out;
    float* out_w   = out + NTOT * 2;
    #pragma unroll
    for (int r = 0; r < 4; r++) {
        int lr = w * 4 + r;
        int n  = n0 + lr;
        const float* hr = &sh[lr * CMID];
        float acc1 = sb2[lane];
        #pragma unroll 8
        for (int cin = 0; cin < CMID; cin++)
            acc1 = fmaf(hr[cin], sW2[cin * 34 + lane], acc1);
        if (lane < 2) {
            out_pos[n * 2 + lane] = pos[n * 2 + lane] + acc1;
            float acc2 = sb2[32 + lane];
            #pragma unroll 8
            for (int cin = 0; cin < CMID; cin++)
                acc2 = fmaf(hr[cin], sW2[cin * 34 + 32 + lane], acc2);
            out_w[n * CC + 30 + lane] = sxn[lr * CC + 30 + lane] + acc2;
        } else {
            out_w[n * CC + lane - 2] = sxn[lr * CC + lane - 2] + acc1;
        }
    }
}

// ---------------- launch ----------------------------------------------------
extern "C" void kernel_launch(void* const* d_in, const int* in_sizes, int n_in,
                              void* d_out, int out_size) {
    const float* positions = (const float*)d_in[0];
    const float* weights   = (const float*)d_in[1];
    const float* kpos = (const float*)d_in[3];
    const float* kw   = (const float*)d_in[4];
    const float* cng  = (const float*)d_in[5];
    const float* cnb  = (const float*)d_in[6];
    const float* W1   = (const float*)d_in[7];
    const float* b1   = (const float*)d_in[8];
    const float* bng  = (const float*)d_in[9];
    const float* bnb  = (const float*)d_in[10];
    const float* W2   = (const float*)d_in[11];
    const float* b2   = (const float*)d_in[12];
    float* out = (float*)d_out;

    cudaFuncSetAttribute(k_hf, cudaFuncAttributeMaxDynamicSharedMemorySize,
                         HF_FLOATS * 4);
    k_prep<<<512, 288>>>(positions, weights, kpos, kw);
    k_main<<<144, 512>>>(positions);
    k_hf<<<HF_GRID, 512, HF_FLOATS * 4>>>(positions, weights, W1, b1,
                                          cng, cnb, bng, bnb, W2, b2, out);
}

// round 12
// speedup vs baseline: 1.2850x; 1.0091x over previous
#include <cuda_runtime.h>
#include <cuda_fp16.h>
#include <cstdint>

#define NTOT 8192
#define BB   8
#define NBAT 1024
#define KK   9
#define CC   32
#define CMID 128
#define MM   9216        // NBAT*KK per batch
#define KSPLIT 9
#define KPART  1024      // MM / KSPLIT
#define NCH    32        // KPART / 32
#define HF_GRID 128
#define PG     16        // n per k_prep block
#define PM     (PG * KK) // 144 m per k_prep block
#define BSTR   36        // sB row stride in words (bank-conflict-free)

// ---------------- scratch (device globals; no allocation anywhere) ----------
__device__ __half  g_convwT[BB * CC * MM];  // [b][c][m], fp16
__device__ float4  g_abxy[BB * MM];         // (am, bx, by, 0) per m
__device__ float   g_part[KSPLIT * NTOT * CC];
__device__ float   g_sx[CC], g_sx2[CC], g_sh[CMID], g_sh2[CMID];
__device__ int     g_cntx;                  // k_hf barrier 0 counter
__device__ int     g_cnth;                  // k_hf barrier 1 counter

// ---------------- helpers ----------------------------------------------------
__device__ __forceinline__ uint32_t ex2h2(float lo, float hi) {
    uint32_t h2, r;
    asm("cvt.rn.f16x2.f32 %0, %1, %2;" : "=r"(h2) : "f"(hi), "f"(lo));
    asm("ex2.approx.f16x2 %0, %1;" : "=r"(r) : "r"(h2));
    return r;
}
__device__ __forceinline__ void mma_f16(float* d,
                                        uint32_t a0, uint32_t a1,
                                        uint32_t a2, uint32_t a3,
                                        uint32_t b0, uint32_t b1) {
    asm volatile(
        "mma.sync.aligned.m16n8k16.row.col.f32.f16.f16.f32 "
        "{%0,%1,%2,%3}, {%4,%5,%6,%7}, {%8,%9}, {%0,%1,%2,%3};"
        : "+f"(d[0]), "+f"(d[1]), "+f"(d[2]), "+f"(d[3])
        : "r"(a0), "r"(a1), "r"(a2), "r"(a3), "r"(b0), "r"(b1));
}

#define LOG2E 1.4426950408889634f
#define C2    (-2.0f * LOG2E)

// ---------------- K1: conv_w^T (fp16) + abxy + zero counters ----------------
// grid 512 (16 n per block), 288 threads = (k=tid/32, d=tid%32)
__global__ void __launch_bounds__(288) k_prep(const float* __restrict__ pos,
                                              const float* __restrict__ wts,
                                              const float* __restrict__ kpos,
                                              const float* __restrict__ kw) {
    __shared__ __align__(16) float sw[PG * CC];       // 2 KB
    __shared__ float sp[PG * 2];
    __shared__ float skp[KK * 2];
    __shared__ float st[PM * 33];                     // 19 KB, [m_local][d] pad33
    int tid = threadIdx.x;
    int n0 = blockIdx.x * PG;          // global n
    int b  = n0 >> 10;
    int m0 = (n0 & 1023) * KK;         // m within batch
    if (blockIdx.x == 0) {             // re-zero per replay
        if (tid < CC)   { g_sx[tid] = 0.f; g_sx2[tid] = 0.f; }
        if (tid < CMID) { g_sh[tid] = 0.f; g_sh2[tid] = 0.f; }
        if (tid == CMID)     g_cntx = 0;
        if (tid == CMID + 1) g_cnth = 0;
    }
    for (int i = tid; i < PG * CC; i += 288) sw[i] = wts[n0 * CC + i];
    if (tid < PG * 2) sp[tid] = pos[n0 * 2 + tid];
    if (tid < KK * 2) skp[tid] = kpos[tid];
    int k = tid / 32, d = tid % 32;
    float kr[CC];
    #pragma unroll
    for (int c = 0; c < CC; c++) kr[c] = kw[(k * CC + c) * CC + d];
    __syncthreads();
    #pragma unroll 4
    for (int n = 0; n < PG; n++) {
        const float4* swr = (const float4*)(sw + n * CC);
        float a = 0.f;
        #pragma unroll
        for (int q = 0; q < 8; q++) {
            float4 v = swr[q];
            a = fmaf(v.x, kr[4*q+0], a);
            a = fmaf(v.y, kr[4*q+1], a);
            a = fmaf(v.z, kr[4*q+2], a);
            a = fmaf(v.w, kr[4*q+3], a);
        }
        st[(n * KK + k) * 33 + d] = a;
    }
    // abxy (144 m's, one per thread)
    if (tid < PM) {
        int n = tid / KK, kk = tid - (tid / KK) * KK;
        float cpx = sp[2 * n]     + skp[2 * kk];
        float cpy = sp[2 * n + 1] + skp[2 * kk + 1];
        float am  = C2 * fmaf(cpx, cpx, cpy * cpy);
        g_abxy[(size_t)b * MM + m0 + tid] =
            make_float4(am, 4.f * LOG2E * cpx, 4.f * LOG2E * cpy, 0.f);
    }
    __syncthreads();
    // transposed writeout: idx = c*144 + mm
    #pragma unroll
    for (int it = 0; it < PM * CC / 288; it++) {
        int idx = tid + it * 288;
        int c  = idx / PM;
        int mm = idx - c * PM;
        g_convwT[((size_t)b * CC + c) * MM + m0 + mm] =
            __float2half_rn(st[mm * 33 + c]);
    }
}

// ---------------- K2: Kmat @ conv_w via mma.sync fp16 (m16n8k16) ------------
// grid 144 = b(8) x rowblock(2) x ksplit(9); 512 threads = 16 warps,
// each warp owns a 32x32 output tile. sB row stride 36 words: B-fragment
// lane banks = (4g + t) -> all 32 distinct (the stride-20 version was an
// 8-way conflict on every fragment load).
__global__ void __launch_bounds__(512) k_main(const float* __restrict__ pos) {
    __shared__ uint32_t sB[2][32 * BSTR]; // fp16 tiles, 4.6 KB each
    __shared__ float4   sAB[2][32];
    int tid  = threadIdx.x;
    int w    = tid >> 5, lane = tid & 31;
    int g    = lane >> 2, t = lane & 3;
    int blk  = blockIdx.x;
    int b   = blk / 18;
    int rem = blk - b * 18;
    int rb  = rem / 9;
    int ks  = rem - rb * 9;
    int ctabase = b * NBAT + rb * 512;
    int rbase   = ctabase + w * 32;
    size_t mbase = (size_t)b * MM + (size_t)ks * KPART;

    int sc = tid >> 3, sq = tid & 7;
    const uint2* gB = (const uint2*)(g_convwT + ((size_t)b * CC + sc) * MM
                                     + (size_t)ks * KPART);
    const float4* gAB = g_abxy + mbase;

    float px[4], py[4], pp[4];
    #pragma unroll
    for (int u = 0; u < 4; u++) {
        float2 p = ((const float2*)pos)[rbase + g + 8 * u];
        px[u] = p.x; py[u] = p.y;
        pp[u] = C2 * fmaf(p.x, p.x, p.y * p.y);
    }
    float acc[2][4][4];
    #pragma unroll
    for (int j = 0; j < 2; j++)
        #pragma unroll
        for (int i = 0; i < 4; i++)
            #pragma unroll
            for (int q = 0; q < 4; q++) acc[j][i][q] = 0.f;

    if (tid < 256) {
        uint2 v = gB[sq];
        sB[0][sc * BSTR + sq * 2]     = v.x;
        sB[0][sc * BSTR + sq * 2 + 1] = v.y;
    }
    if (tid < 32) sAB[0][tid] = gAB[tid];
    for (int tc = 0; tc < NCH; tc++) {
        int buf = tc & 1;
        __syncthreads();
        if (tc + 1 < NCH) {
            if (tid < 256) {
                uint2 v = gB[(tc + 1) * 8 + sq];
                sB[buf ^ 1][sc * BSTR + sq * 2]     = v.x;
                sB[buf ^ 1][sc * BSTR + sq * 2 + 1] = v.y;
            }
            if (tid < 32) sAB[buf ^ 1][tid] = gAB[(tc + 1) * 32 + tid];
        }
        uint32_t A16[4][4];
        #pragma unroll
        for (int v = 0; v < 4; v++) {
            float4 qa = sAB[buf][2 * t + 8 * v];
            float4 qb = sAB[buf][2 * t + 8 * v + 1];
            #pragma unroll
            for (int u = 0; u < 4; u++) {
                float lo = fmaf(qa.y, px[u], fmaf(qa.z, py[u], pp[u] + qa.x));
                float hi = fmaf(qb.y, px[u], fmaf(qb.z, py[u], pp[u] + qb.x));
                A16[u][v] = ex2h2(lo, hi);
            }
        }
        #pragma unroll
        for (int i = 0; i < 4; i++) {
            int base = (i * 8 + g) * BSTR;
            #pragma unroll
            for (int s = 0; s < 2; s++) {
                uint32_t b0 = sB[buf][base + 8 * s + t];
                uint32_t b1 = sB[buf][base + 8 * s + t + 4];
                #pragma unroll
                for (int j = 0; j < 2; j++)
                    mma_f16(acc[j][i],
                            A16[2*j][2*s],   A16[2*j+1][2*s],
                            A16[2*j][2*s+1], A16[2*j+1][2*s+1],
                            b0, b1);
            }
        }
    }
    #pragma unroll
    for (int j = 0; j < 2; j++) {
        int nr0 = rbase + j * 16 + g;
        #pragma unroll
        for (int i = 0; i < 4; i++) {
            int c = i * 8 + t * 2;
            *(float2*)&g_part[((size_t)ks * NTOT + nr0) * CC + c] =
                make_float2(acc[j][i][0], acc[j][i][1]);
            *(float2*)&g_part[((size_t)ks * NTOT + nr0 + 8) * CC + c] =
                make_float2(acc[j][i][2], acc[j][i][3]);
        }
    }
}

// ---------------- K3: reduce -> x-stats -> xn -> h -> BN(h) -> W2 -> out ----
// grid 128, 512 threads; 64 rows/block; TWO grid-wide spin barriers.
#define HF_SXN  0        // 64*32   = 2048
#define HF_SW1  2048     // 32*128  = 4096
#define HF_SH   6144     // 64*128  = 8192
#define HF_SW2  14336    // 128*34  = 4352
#define HF_SB2  18688    // 48
#define HF_SXS  18736    // 32
#define HF_SXH  18768    // 32
#define HF_SHS  18800    // 128
#define HF_SHH  18928    // 128
#define HF_RED  19056    // 512
#define HF_FLOATS 19568  // 78272 bytes

__global__ void __launch_bounds__(512) k_hf(const float* __restrict__ pos,
                                            const float* __restrict__ wts,
                                            const float* __restrict__ W1,
                                            const float* __restrict__ b1,
                                            const float* __restrict__ cng,
                                            const float* __restrict__ cnb,
                                            const float* __restrict__ bng,
                                            const float* __restrict__ bnb,
                                            const float* __restrict__ W2,
                                            const float* __restrict__ b2,
                                            float* __restrict__ out) {
    extern __shared__ float dyn[];
    float* sxn = dyn + HF_SXN;
    float* sW1 = dyn + HF_SW1;
    float* sh  = dyn + HF_SH;
    float* sW2 = dyn + HF_SW2;
    float* sb2 = dyn + HF_SB2;
    float* sxs = dyn + HF_SXS;
    float* sxh = dyn + HF_SXH;
    float* shs = dyn + HF_SHS;
    float* shh = dyn + HF_SHH;
    float* red = dyn + HF_RED;
    int tid = threadIdx.x;
    int n0 = blockIdx.x * 64;
    #pragma unroll
    for (int i = 0; i < 8; i++) sW1[tid + 512 * i] = W1[tid + 512 * i];
    for (int i = tid; i < CMID * 34; i += 512) sW2[i] = W2[i];
    if (tid < 34) sb2[tid] = b2[tid];
    // ---- phase 0: reduce KSPLIT partials, leaky, local x into smem ----
    {
        int n = tid >> 3, c4 = (tid & 7) * 4;
        const float4* base = (const float4*)(g_part
                              + (size_t)(n0 + n) * CC + c4);
        float4 a = base[0];
        #pragma unroll
        for (int s = 1; s < KSPLIT; s++) {
            float4 v = base[(size_t)s * (NTOT * CC / 4)];
            a.x += v.x; a.y += v.y; a.z += v.z; a.w += v.w;
        }
        a.x = a.x >= 0.f ? a.x : 0.01f * a.x;
        a.y = a.y >= 0.f ? a.y : 0.01f * a.y;
        a.z = a.z >= 0.f ? a.z : 0.01f * a.z;
        a.w = a.w >= 0.f ? a.w : 0.01f * a.w;
        *(float4*)&sxn[n * CC + c4] = a;
    }
    __syncthreads();
    {
        int c = tid & 31, rs = tid >> 5;
        float sx = 0.f, sx2 = 0.f;
        #pragma unroll
        for (int i = 0; i < 4; i++) {
            float v = sxn[(rs + 16 * i) * CC + c];
            sx += v; sx2 += v * v;
        }
        red[tid] = sx; __syncthreads();
        if (rs == 0) {
            float s = 0.f;
            #pragma unroll
            for (int j = 0; j < 16; j++) s += red[c + 32 * j];
            atomicAdd(&g_sx[c], s);
        }
        __syncthreads(); red[tid] = sx2; __syncthreads();
        if (rs == 0) {
            float s = 0.f;
            #pragma unroll
            for (int j = 0; j < 16; j++) s += red[c + 32 * j];
            atomicAdd(&g_sx2[c], s);
        }
    }
    __threadfence();
    __syncthreads();
    if (tid == 0) {
        atomicAdd(&g_cntx, 1);
        while (*(volatile int*)&g_cntx < HF_GRID) { }
    }
    __syncthreads();
    __threadfence();
    if (tid < CC) {
        float mu  = g_sx[tid] * (1.f / NTOT);
        float var = fmaf(-mu, mu, g_sx2[tid] * (1.f / NTOT));
        float rsv = rsqrtf(var + 1e-5f);
        float gs  = cng[tid] * rsv;
        sxs[tid] = gs;
        sxh[tid] = fmaf(-gs, mu, cnb[tid]);
    }
    __syncthreads();
    #pragma unroll
    for (int i = 0; i < 4; i++) {
        int idx = tid + 512 * i;
        int rr = idx >> 5, c = idx & 31;
        sxn[idx] = fmaf(sxs[c], sxn[idx], sxh[c])
                   + wts[(size_t)(n0 + rr) * CC + c];
    }
    __syncthreads();
    int c = tid & 127, rg = tid >> 7;
    float wreg[CC];
    #pragma unroll
    for (int cin = 0; cin < CC; cin++) wreg[cin] = sW1[cin * CMID + c];
    float bc = b1[c];
    float shsum = 0.f, sh2sum = 0.f;
    for (int i = 0; i < 16; i++) {
        int rr = rg + 4 * i;
        const float4* xr4 = (const float4*)&sxn[rr * CC];
        float a0 = bc, a1 = 0.f;
        #pragma unroll
        for (int q = 0; q < 4; q++) {
            float4 v0 = xr4[q], v1 = xr4[q + 4];
            a0 = fmaf(v0.x, wreg[4*q+0],  a0);
            a1 = fmaf(v1.x, wreg[16+4*q+0], a1);
            a0 = fmaf(v0.y, wreg[4*q+1],  a0);
            a1 = fmaf(v1.y, wreg[16+4*q+1], a1);
            a0 = fmaf(v0.z, wreg[4*q+2],  a0);
            a1 = fmaf(v1.z, wreg[16+4*q+2], a1);
            a0 = fmaf(v0.w, wreg[4*q+3],  a0);
            a1 = fmaf(v1.w, wreg[16+4*q+3], a1);
        }
        float a = a0 + a1;
        float hh = a >= 0.f ? a : 0.01f * a;
        sh[rr * CMID + c] = hh;
        shsum += hh; sh2sum += hh * hh;
    }
    red[tid] = shsum; __syncthreads();
    if (rg == 0) atomicAdd(&g_sh[c], red[c] + red[c + 128] + red[c + 256] + red[c + 384]);
    __syncthreads(); red[tid] = sh2sum; __syncthreads();
    if (rg == 0) atomicAdd(&g_sh2[c], red[c] + red[c + 128] + red[c + 256] + red[c + 384]);
    __threadfence();
    __syncthreads();
    if (tid == 0) {
        atomicAdd(&g_cnth, 1);
        while (*(volatile int*)&g_cnth < HF_GRID) { }
    }
    __syncthreads();
    __threadfence();
    if (tid < CMID) {
        float mu  = g_sh[tid] * (1.f / NTOT);
        float var = fmaf(-mu, mu, g_sh2[tid] * (1.f / NTOT));
        float rsv = rsqrtf(var + 1e-5f);
        float gs  = bng[tid] * rsv;
        shs[tid] = gs;
        shh[tid] = fmaf(-gs, mu, bnb[tid]);
    }
    __syncthreads();
    #pragma unroll
    for (int i = 0; i < 16; i++) {
        int idx = tid + 512 * i;
        int cc = idx & 127;
        sh[idx] = fmaf(shs[cc], sh[idx], shh[cc]);
    }
    __syncthreads();
    int w = tid >> 5, lane = tid & 31;
    float* out_pos = out;
    float* out_w   = out + NTOT * 2;
    #pragma unroll
    for (int r = 0; r < 4; r++) {
        int lr = w * 4 + r;
        int n  = n0 + lr;
        const float* hr = &sh[lr * CMID];
        float acc1 = sb2[lane];
        #pragma unroll 8
        for (int cin = 0; cin < CMID; cin++)
            acc1 = fmaf(hr[cin], sW2[cin * 34 + lane], acc1);
        if (lane < 2) {
            out_pos[n * 2 + lane] = pos[n * 2 + lane] + acc1;
            float acc2 = sb2[32 + lane];
            #pragma unroll 8
            for (int cin = 0; cin < CMID; cin++)
                acc2 = fmaf(hr[cin], sW2[cin * 34 + 32 + lane], acc2);
            out_w[n * CC + 30 + lane] = sxn[lr * CC + 30 + lane] + acc2;
        } else {
            out_w[n * CC + lane - 2] = sxn[lr * CC + lane - 2] + acc1;
        }
    }
}

// ---------------- launch ----------------------------------------------------
extern "C" void kernel_launch(void* const* d_in, const int* in_sizes, int n_in,
                              void* d_out, int out_size) {
    const float* positions = (const float*)d_in[0];
    const float* weights   = (const float*)d_in[1];
    const float* kpos = (const float*)d_in[3];
    const float* kw   = (const float*)d_in[4];
    const float* cng  = (const float*)d_in[5];
    const float* cnb  = (const float*)d_in[6];
    const float* W1   = (const float*)d_in[7];
    const float* b1   = (const float*)d_in[8];
    const float* bng  = (const float*)d_in[9];
    const float* bnb  = (const float*)d_in[10];
    const float* W2   = (const float*)d_in[11];
    const float* b2   = (const float*)d_in[12];
    float* out = (float*)d_out;

    cudaFuncSetAttribute(k_hf, cudaFuncAttributeMaxDynamicSharedMemorySize,
                         HF_FLOATS * 4);
    k_prep<<<512, 288>>>(positions, weights, kpos, kw);
    k_main<<<144, 512>>>(positions);
    k_hf<<<HF_GRID, 512, HF_FLOATS * 4>>>(positions, weights, W1, b1,
                                          cng, cnb, bng, bnb, W2, b2, out);
}

// round 13
// speedup vs baseline: 1.4135x; 1.1000x over previous
#include <cuda_runtime.h>
#include <cuda_fp16.h>
#include <cstdint>

#define NTOT 8192
#define BB   8
#define NBAT 1024
#define KK   9
#define CC   32
#define CMID 128
#define MM   9216        // NBAT*KK per batch
#define KSPLIT 9
#define KPART  1024      // MM / KSPLIT
#define NCH    32        // KPART / 32
#define HF_GRID 128
#define BSTR   36        // k_main sB row stride in words

// ---------------- scratch (device globals; no allocation anywhere) ----------
__device__ __half  g_convwT[BB * CC * MM];  // [b][c][m], fp16
__device__ float4  g_abxy[BB * MM];         // (am, bx, by, 0) per m
__device__ float   g_part[KSPLIT * NTOT * CC];
__device__ float   g_sx[CC], g_sx2[CC], g_sh[CMID], g_sh2[CMID];
__device__ int     g_cntx;                  // k_hf barrier 0 counter
__device__ int     g_cnth;                  // k_hf barrier 1 counter

// ---------------- helpers ----------------------------------------------------
__device__ __forceinline__ uint32_t ex2h2(float lo, float hi) {
    uint32_t h2, r;
    asm("cvt.rn.f16x2.f32 %0, %1, %2;" : "=r"(h2) : "f"(hi), "f"(lo));
    asm("ex2.approx.f16x2 %0, %1;" : "=r"(r) : "r"(h2));
    return r;
}
__device__ __forceinline__ uint32_t packh2(float lo, float hi) {
    uint32_t h2;
    asm("cvt.rn.f16x2.f32 %0, %1, %2;" : "=r"(h2) : "f"(hi), "f"(lo));
    return h2;
}
__device__ __forceinline__ void mma_f16(float* d,
                                        uint32_t a0, uint32_t a1,
                                        uint32_t a2, uint32_t a3,
                                        uint32_t b0, uint32_t b1) {
    asm volatile(
        "mma.sync.aligned.m16n8k16.row.col.f32.f16.f16.f32 "
        "{%0,%1,%2,%3}, {%4,%5,%6,%7}, {%8,%9}, {%0,%1,%2,%3};"
        : "+f"(d[0]), "+f"(d[1]), "+f"(d[2]), "+f"(d[3])
        : "r"(a0), "r"(a1), "r"(a2), "r"(a3), "r"(b0), "r"(b1));
}

#define LOG2E 1.4426950408889634f
#define C2    (-2.0f * LOG2E)

// ---------------- K1: conv_w via fp16 MMA + abxy + zero counters ------------
// grid 128 (64 n per block), 256 threads = 8 warps (4 row-groups x 2 col-groups)
// GEMM: conv_w[64 x 288] = wts[64 x 32] @ kw'[32 x 288], cols j = k*32+d.
// Dynamic smem layout (uint32 words):
#define PS_SKW  0        // 288*20 = 5760  (B: [j][c-pair], fp16)
#define PS_SW   5760     // 64*20  = 1280  (A: [n][c-pair], fp16)
#define PS_ST   7040     // 64*148 = 9472  (out staging: [n][col-pair], fp16)
#define PS_SP   16512    // 128 floats
#define PS_SKP  16640    // 18 floats
#define PS_WORDS 16660   // 66640 bytes

__global__ void __launch_bounds__(256) k_prep(const float* __restrict__ pos,
                                              const float* __restrict__ wts,
                                              const float* __restrict__ kpos,
                                              const float* __restrict__ kw) {
    extern __shared__ uint32_t ps[];
    uint32_t* skw = ps + PS_SKW;
    uint32_t* sw  = ps + PS_SW;
    uint32_t* st  = ps + PS_ST;
    float*  sp  = (float*)(ps + PS_SP);
    float*  skp = (float*)(ps + PS_SKP);
    __half* skwh = (__half*)skw;
    __half* sth  = (__half*)st;
    int tid = threadIdx.x;
    int n0 = blockIdx.x * 64;          // global n
    int b  = n0 >> 10;
    int m0 = (n0 & 1023) * KK;         // m within batch
    if (blockIdx.x == 0) {             // re-zero per replay
        if (tid < CC)   { g_sx[tid] = 0.f; g_sx2[tid] = 0.f; }
        if (tid < CMID) { g_sh[tid] = 0.f; g_sh2[tid] = 0.f; }
        if (tid == CMID)     g_cntx = 0;
        if (tid == CMID + 1) g_cnth = 0;
    }
    // A: wts rows -> sw fp16 pairs (coalesced float2 loads)
    #pragma unroll
    for (int i = 0; i < 4; i++) {
        int wdx = tid + 256 * i;       // 0..1023 (64 rows x 16 pairs)
        int n = wdx >> 4, cp = wdx & 15;
        float2 v = ((const float2*)wts)[(size_t)(n0 + n) * 16 + cp];
        sw[n * 20 + cp] = packh2(v.x, v.y);
    }
    // B: kw -> skw fp16, transposed to [j=k*32+d][c] (coalesced loads over d)
    #pragma unroll
    for (int i = 0; i < 36; i++) {
        int flat = tid + 256 * i;      // 0..9215
        int d = flat & 31, c = (flat >> 5) & 31, k = flat >> 10;
        skwh[(k * 32 + d) * 40 + c] = __float2half_rn(kw[flat]);
    }
    if (tid < 128) sp[tid] = pos[n0 * 2 + tid];
    if (tid < KK * 2) skp[tid] = kpos[tid];
    __syncthreads();
    // abxy: 576 m's
    #pragma unroll
    for (int i = 0; i < 3; i++) {
        int idx = tid + 256 * i;
        if (idx < 576) {
            int n = idx / KK, kk2 = idx - KK * (idx / KK);
            float cpx = sp[2 * n]     + skp[2 * kk2];
            float cpy = sp[2 * n + 1] + skp[2 * kk2 + 1];
            float am  = C2 * fmaf(cpx, cpx, cpy * cpy);
            g_abxy[(size_t)b * MM + m0 + idx] =
                make_float4(am, 4.f * LOG2E * cpx, 4.f * LOG2E * cpy, 0.f);
        }
    }
    // MMA phase: warp (wr, wc): rows 16*wr.., cols wc*144 + i*8 (18 tiles)
    int w = tid >> 5, lane = tid & 31;
    int g = lane >> 2, t = lane & 3;
    int wr = w & 3, wc = w >> 2;
    int arow0 = (16 * wr + g) * 20;
    int arow1 = (16 * wr + g + 8) * 20;
    float acc[18][4];
    #pragma unroll
    for (int i = 0; i < 18; i++)
        #pragma unroll
        for (int q = 0; q < 4; q++) acc[i][q] = 0.f;
    #pragma unroll
    for (int s = 0; s < 2; s++) {
        uint32_t a0 = sw[arow0 + t + 8 * s];
        uint32_t a1 = sw[arow1 + t + 8 * s];
        uint32_t a2 = sw[arow0 + t + 8 * s + 4];
        uint32_t a3 = sw[arow1 + t + 8 * s + 4];
        #pragma unroll
        for (int i = 0; i < 18; i++) {
            int brow = (wc * 144 + i * 8 + g) * 20;
            uint32_t b0 = skw[brow + 8 * s + t];
            uint32_t b1 = skw[brow + 8 * s + t + 4];
            mma_f16(acc[i], a0, a1, a2, a3, b0, b1);
        }
    }
    // stage: frag (rows 16wr+g/+8, cols wc*144+i*8+2t,+1) -> st half2
    #pragma unroll
    for (int i = 0; i < 18; i++) {
        int cpair = wc * 72 + i * 4 + t;
        st[(16 * wr + g) * 148 + cpair]     = packh2(acc[i][0], acc[i][1]);
        st[(16 * wr + g + 8) * 148 + cpair] = packh2(acc[i][2], acc[i][3]);
    }
    __syncthreads();
    // transposed writeout: convwT[b][c][m0+mm] = st[n=mm/9][ (mm%9)*32 + c ]
    // .32 stores of m-pairs, perfectly coalesced over flat index.
    #pragma unroll
    for (int i = 0; i < 36; i++) {
        int flat = tid + 256 * i;      // 0..9215 (288 m-pairs x 32 c)
        int c  = flat / 288;
        int mp = flat - c * 288;
        int mm = 2 * mp;
        int n1 = mm / KK, k1 = mm - KK * n1;
        int mmb = mm + 1;
        int n2 = mmb / KK, k2 = mmb - KK * n2;
        __half v0 = sth[n1 * 296 + k1 * 32 + c];
        __half v1 = sth[n2 * 296 + k2 * 32 + c];
        __half2 pv = __halves2half2(v0, v1);
        *(uint32_t*)((__half*)g_convwT + ((size_t)b * CC + c) * MM + m0 + mm) =
            *(uint32_t*)&pv;
    }
}

// ---------------- K2: Kmat @ conv_w via mma.sync fp16 (m16n8k16) ------------
// grid 144 = b(8) x rowblock(2) x ksplit(9); 512 threads = 16 warps,
// each warp owns a 32x32 output tile. (unchanged — verified)
__global__ void __launch_bounds__(512) k_main(const float* __restrict__ pos) {
    __shared__ uint32_t sB[2][32 * BSTR];
    __shared__ float4   sAB[2][32];
    int tid  = threadIdx.x;
    int w    = tid >> 5, lane = tid & 31;
    int g    = lane >> 2, t = lane & 3;
    int blk  = blockIdx.x;
    int b   = blk / 18;
    int rem = blk - b * 18;
    int rb  = rem / 9;
    int ks  = rem - rb * 9;
    int ctabase = b * NBAT + rb * 512;
    int rbase   = ctabase + w * 32;
    size_t mbase = (size_t)b * MM + (size_t)ks * KPART;

    int sc = tid >> 3, sq = tid & 7;
    const uint2* gB = (const uint2*)(g_convwT + ((size_t)b * CC + sc) * MM
                                     + (size_t)ks * KPART);
    const float4* gAB = g_abxy + mbase;

    float px[4], py[4], pp[4];
    #pragma unroll
    for (int u = 0; u < 4; u++) {
        float2 p = ((const float2*)pos)[rbase + g + 8 * u];
        px[u] = p.x; py[u] = p.y;
        pp[u] = C2 * fmaf(p.x, p.x, p.y * p.y);
    }
    float acc[2][4][4];
    #pragma unroll
    for (int j = 0; j < 2; j++)
        #pragma unroll
        for (int i = 0; i < 4; i++)
            #pragma unroll
            for (int q = 0; q < 4; q++) acc[j][i][q] = 0.f;

    if (tid < 256) {
        uint2 v = gB[sq];
        sB[0][sc * BSTR + sq * 2]     = v.x;
        sB[0][sc * BSTR + sq * 2 + 1] = v.y;
    }
    if (tid < 32) sAB[0][tid] = gAB[tid];
    for (int tc = 0; tc < NCH; tc++) {
        int buf = tc & 1;
        __syncthreads();
        if (tc + 1 < NCH) {
            if (tid < 256) {
                uint2 v = gB[(tc + 1) * 8 + sq];
                sB[buf ^ 1][sc * BSTR + sq * 2]     = v.x;
                sB[buf ^ 1][sc * BSTR + sq * 2 + 1] = v.y;
            }
            if (tid < 32) sAB[buf ^ 1][tid] = gAB[(tc + 1) * 32 + tid];
        }
        uint32_t A16[4][4];
        #pragma unroll
        for (int v = 0; v < 4; v++) {
            float4 qa = sAB[buf][2 * t + 8 * v];
            float4 qb = sAB[buf][2 * t + 8 * v + 1];
            #pragma unroll
            for (int u = 0; u < 4; u++) {
                float lo = fmaf(qa.y, px[u], fmaf(qa.z, py[u], pp[u] + qa.x));
                float hi = fmaf(qb.y, px[u], fmaf(qb.z, py[u], pp[u] + qb.x));
                A16[u][v] = ex2h2(lo, hi);
            }
        }
        #pragma unroll
        for (int i = 0; i < 4; i++) {
            int base = (i * 8 + g) * BSTR;
            #pragma unroll
            for (int s = 0; s < 2; s++) {
                uint32_t b0 = sB[buf][base + 8 * s + t];
                uint32_t b1 = sB[buf][base + 8 * s + t + 4];
                #pragma unroll
                for (int j = 0; j < 2; j++)
                    mma_f16(acc[j][i],
                            A16[2*j][2*s],   A16[2*j+1][2*s],
                            A16[2*j][2*s+1], A16[2*j+1][2*s+1],
                            b0, b1);
            }
        }
    }
    #pragma unroll
    for (int j = 0; j < 2; j++) {
        int nr0 = rbase + j * 16 + g;
        #pragma unroll
        for (int i = 0; i < 4; i++) {
            int c = i * 8 + t * 2;
            *(float2*)&g_part[((size_t)ks * NTOT + nr0) * CC + c] =
                make_float2(acc[j][i][0], acc[j][i][1]);
            *(float2*)&g_part[((size_t)ks * NTOT + nr0 + 8) * CC + c] =
                make_float2(acc[j][i][2], acc[j][i][3]);
        }
    }
}

// ---------------- K3: reduce -> x-stats -> xn -> h -> BN(h) -> W2 -> out ----
// grid 128, 512 threads; 64 rows/block; TWO grid-wide spin barriers.
#define HF_SXN  0        // 64*32   = 2048
#define HF_SW1  2048     // 32*128  = 4096
#define HF_SH   6144     // 64*128  = 8192
#define HF_SW2  14336    // 128*34  = 4352
#define HF_SB2  18688    // 48
#define HF_SXS  18736    // 32
#define HF_SXH  18768    // 32
#define HF_SHS  18800    // 128
#define HF_SHH  18928    // 128
#define HF_RED  19056    // 512
#define HF_FLOATS 19568  // 78272 bytes

__global__ void __launch_bounds__(512) k_hf(const float* __restrict__ pos,
                                            const float* __restrict__ wts,
                                            const float* __restrict__ W1,
                                            const float* __restrict__ b1,
                                            const float* __restrict__ cng,
                                            const float* __restrict__ cnb,
                                            const float* __restrict__ bng,
                                            const float* __restrict__ bnb,
                                            const float* __restrict__ W2,
                                            const float* __restrict__ b2,
                                            float* __restrict__ out) {
    extern __shared__ float dyn[];
    float* sxn = dyn + HF_SXN;
    float* sW1 = dyn + HF_SW1;
    float* sh  = dyn + HF_SH;
    float* sW2 = dyn + HF_SW2;
    float* sb2 = dyn + HF_SB2;
    float* sxs = dyn + HF_SXS;
    float* sxh = dyn + HF_SXH;
    float* shs = dyn + HF_SHS;
    float* shh = dyn + HF_SHH;
    float* red = dyn + HF_RED;
    int tid = threadIdx.x;
    int n0 = blockIdx.x * 64;
    #pragma unroll
    for (int i = 0; i < 8; i++) sW1[tid + 512 * i] = W1[tid + 512 * i];
    for (int i = tid; i < CMID * 34; i += 512) sW2[i] = W2[i];
    if (tid < 34) sb2[tid] = b2[tid];
    {
        int n = tid >> 3, c4 = (tid & 7) * 4;
        const float4* base = (const float4*)(g_part
                              + (size_t)(n0 + n) * CC + c4);
        float4 a = base[0];
        #pragma unroll
        for (int s = 1; s < KSPLIT; s++) {
            float4 v = base[(size_t)s * (NTOT * CC / 4)];
            a.x += v.x; a.y += v.y; a.z += v.z; a.w += v.w;
        }
        a.x = a.x >= 0.f ? a.x : 0.01f * a.x;
        a.y = a.y >= 0.f ? a.y : 0.01f * a.y;
        a.z = a.z >= 0.f ? a.z : 0.01f * a.z;
        a.w = a.w >= 0.f ? a.w : 0.01f * a.w;
        *(float4*)&sxn[n * CC + c4] = a;
    }
    __syncthreads();
    {
        int c = tid & 31, rs = tid >> 5;
        float sx = 0.f, sx2 = 0.f;
        #pragma unroll
        for (int i = 0; i < 4; i++) {
            float v = sxn[(rs + 16 * i) * CC + c];
            sx += v; sx2 += v * v;
        }
        red[tid] = sx; __syncthreads();
        if (rs == 0) {
            float s = 0.f;
            #pragma unroll
            for (int j = 0; j < 16; j++) s += red[c + 32 * j];
            atomicAdd(&g_sx[c], s);
        }
        __syncthreads(); red[tid] = sx2; __syncthreads();
        if (rs == 0) {
            float s = 0.f;
            #pragma unroll
            for (int j = 0; j < 16; j++) s += red[c + 32 * j];
            atomicAdd(&g_sx2[c], s);
        }
    }
    __threadfence();
    __syncthreads();
    if (tid == 0) {
        atomicAdd(&g_cntx, 1);
        while (*(volatile int*)&g_cntx < HF_GRID) { }
    }
    __syncthreads();
    __threadfence();
    if (tid < CC) {
        float mu  = g_sx[tid] * (1.f / NTOT);
        float var = fmaf(-mu, mu, g_sx2[tid] * (1.f / NTOT));
        float rsv = rsqrtf(var + 1e-5f);
        float gs  = cng[tid] * rsv;
        sxs[tid] = gs;
        sxh[tid] = fmaf(-gs, mu, cnb[tid]);
    }
    __syncthreads();
    #pragma unroll
    for (int i = 0; i < 4; i++) {
        int idx = tid + 512 * i;
        int rr = idx >> 5, c = idx & 31;
        sxn[idx] = fmaf(sxs[c], sxn[idx], sxh[c])
                   + wts[(size_t)(n0 + rr) * CC + c];
    }
    __syncthreads();
    int c = tid & 127, rg = tid >> 7;
    float wreg[CC];
    #pragma unroll
    for (int cin = 0; cin < CC; cin++) wreg[cin] = sW1[cin * CMID + c];
    float bc = b1[c];
    float shsum = 0.f, sh2sum = 0.f;
    for (int i = 0; i < 16; i++) {
        int rr = rg + 4 * i;
        const float4* xr4 = (const float4*)&sxn[rr * CC];
        float a0 = bc, a1 = 0.f;
        #pragma unroll
        for (int q = 0; q < 4; q++) {
            float4 v0 = xr4[q], v1 = xr4[q + 4];
            a0 = fmaf(v0.x, wreg[4*q+0],  a0);
            a1 = fmaf(v1.x, wreg[16+4*q+0], a1);
            a0 = fmaf(v0.y, wreg[4*q+1],  a0);
            a1 = fmaf(v1.y, wreg[16+4*q+1], a1);
            a0 = fmaf(v0.z, wreg[4*q+2],  a0);
            a1 = fmaf(v1.z, wreg[16+4*q+2], a1);
            a0 = fmaf(v0.w, wreg[4*q+3],  a0);
            a1 = fmaf(v1.w, wreg[16+4*q+3], a1);
        }
        float a = a0 + a1;
        float hh = a >= 0.f ? a : 0.01f * a;
        sh[rr * CMID + c] = hh;
        shsum += hh; sh2sum += hh * hh;
    }
    red[tid] = shsum; __syncthreads();
    if (rg == 0) atomicAdd(&g_sh[c], red[c] + red[c + 128] + red[c + 256] + red[c + 384]);
    __syncthreads(); red[tid] = sh2sum; __syncthreads();
    if (rg == 0) atomicAdd(&g_sh2[c], red[c] + red[c + 128] + red[c + 256] + red[c + 384]);
    __threadfence();
    __syncthreads();
    if (tid == 0) {
        atomicAdd(&g_cnth, 1);
        while (*(volatile int*)&g_cnth < HF_GRID) { }
    }
    __syncthreads();
    __threadfence();
    if (tid < CMID) {
        float mu  = g_sh[tid] * (1.f / NTOT);
        float var = fmaf(-mu, mu, g_sh2[tid] * (1.f / NTOT));
        float rsv = rsqrtf(var + 1e-5f);
        float gs  = bng[tid] * rsv;
        shs[tid] = gs;
        shh[tid] = fmaf(-gs, mu, bnb[tid]);
    }
    __syncthreads();
    #pragma unroll
    for (int i = 0; i < 16; i++) {
        int idx = tid + 512 * i;
        int cc = idx & 127;
        sh[idx] = fmaf(shs[cc], sh[idx], shh[cc]);
    }
    __syncthreads();
    int w = tid >> 5, lane = tid & 31;
    float* out_pos = out;
    float* out_w   = out + NTOT * 2;
    #pragma unroll
    for (int r = 0; r < 4; r++) {
        int lr = w * 4 + r;
        int n  = n0 + lr;
        const float* hr = &sh[lr * CMID];
        float acc1 = sb2[lane];
        #pragma unroll 8
        for (int cin = 0; cin < CMID; cin++)
            acc1 = fmaf(hr[cin], sW2[cin * 34 + lane], acc1);
        if (lane < 2) {
            out_pos[n * 2 + lane] = pos[n * 2 + lane] + acc1;
            float acc2 = sb2[32 + lane];
            #pragma unroll 8
            for (int cin = 0; cin < CMID; cin++)
                acc2 = fmaf(hr[cin], sW2[cin * 34 + 32 + lane], acc2);
            out_w[n * CC + 30 + lane] = sxn[lr * CC + 30 + lane] + acc2;
        } else {
            out_w[n * CC + lane - 2] = sxn[lr * CC + lane - 2] + acc1;
        }
    }
}

// ---------------- launch ----------------------------------------------------
extern "C" void kernel_launch(void* const* d_in, const int* in_sizes, int n_in,
                              void* d_out, int out_size) {
    const float* positions = (const float*)d_in[0];
    const float* weights   = (const float*)d_in[1];
    const float* kpos = (const float*)d_in[3];
    const float* kw   = (const float*)d_in[4];
    const float* cng  = (const float*)d_in[5];
    const float* cnb  = (const float*)d_in[6];
    const float* W1   = (const float*)d_in[7];
    const float* b1   = (const float*)d_in[8];
    const float* bng  = (const float*)d_in[9];
    const float* bnb  = (const float*)d_in[10];
    const float* W2   = (const float*)d_in[11];
    const float* b2   = (const float*)d_in[12];
    float* out = (float*)d_out;

    cudaFuncSetAttribute(k_prep, cudaFuncAttributeMaxDynamicSharedMemorySize,
                         PS_WORDS * 4);
    cudaFuncSetAttribute(k_hf, cudaFuncAttributeMaxDynamicSharedMemorySize,
                         HF_FLOATS * 4);
    k_prep<<<128, 256, PS_WORDS * 4>>>(positions, weights, kpos, kw);
    k_main<<<144, 512>>>(positions);
    k_hf<<<HF_GRID, 512, HF_FLOATS * 4>>>(positions, weights, W1, b1,
                                          cng, cnb, bng, bnb, W2, b2, out);
}